// round 12
// baseline (speedup 1.0000x reference)
#include <cuda_runtime.h>
#include <cstdint>

#define SLEN 128
#define BSZ  16
#define EMB  512
#define NHEAD 8
#define HDIM 64
#define BH   (BSZ*NHEAD)   // 128
#define NEG_INF (-1e9f)
#define SCALING 0.125f     // 1/sqrt(64)

// ---- f32x2 packed math (Blackwell) ----
#define FMA2(d, a, b) asm("fma.rn.f32x2 %0, %1, %2, %0;" : "+l"(d) : "l"(a), "l"(b))
#define PACK2(u, lo, hi) asm("mov.b64 %0, {%1, %2};" : "=l"(u) : "f"(lo), "f"(hi))
#define UNPACK2(lo, hi, u) asm("mov.b64 {%0, %1}, %2;" : "=f"(lo), "=f"(hi) : "l"(u))

typedef unsigned long long ull_t;

__device__ __forceinline__ void cpa16(uint32_t saddr, const void* gaddr) {
    asm volatile("cp.async.ca.shared.global [%0], [%1], 16;" :: "r"(saddr), "l"(gaddr));
}
__device__ __forceinline__ void cpa_commit() {
    asm volatile("cp.async.commit_group;");
}
__device__ __forceinline__ void cpa_wait_all() {
    asm volatile("cp.async.wait_group 0;");
}

// ---------------- scratch (device globals; no runtime alloc) ----------------
__device__ float g_q[BH*SLEN*HDIM];        // [b][i][d]
__device__ float g_k[BH*SLEN*HDIM];        // [b][j][d]
__device__ float g_v[BH*SLEN*HDIM];        // [b][j][d]
__device__ float g_r[SLEN*BSZ*EMB];        // [m][e]
__device__ float g_qW[BH*SLEN*EMB];        // [b][i][e]
__device__ float g_aw[BH*SLEN*SLEN];       // [b][i][j]  (qk base, then normalized aw)
__device__ float g_s[BH*SLEN*EMB];         // [b][i][e]
__device__ float g_attn[SLEN*BSZ*EMB];     // [m][e]

// ---------------- K1: fused projections  C = X(2048x512) @ W^T --------------
// (round-9 measured version)
__global__ __launch_bounds__(256) void k1_proj(const float* __restrict__ x,
                                               const float* __restrict__ Wq,
                                               const float* __restrict__ Wk,
                                               const float* __restrict__ Wv,
                                               const float* __restrict__ Wskip) {
    __shared__ float As[16][128];
    __shared__ float Bs[16][128];
    const int m0 = blockIdx.y * 128;
    const int c0 = blockIdx.x * 128;
    const int sel = c0 >> 9;
    const float* W = (sel == 0) ? Wq : (sel == 1) ? Wk : (sel == 2) ? Wv : Wskip;
    const int e0 = c0 & 511;

    const int t  = threadIdx.x;
    const int ty = t >> 4, tx = t & 15;
    const int lr = t >> 1;
    const int lc = (t & 1) * 8;

    ull_t acc2[8][4];
#pragma unroll
    for (int a = 0; a < 8; a++)
#pragma unroll
        for (int b = 0; b < 4; b++) acc2[a][b] = 0ull;

    for (int k0 = 0; k0 < 512; k0 += 16) {
        float4 a0 = *(const float4*)(x + (size_t)(m0 + lr) * 512 + k0 + lc);
        float4 a1 = *(const float4*)(x + (size_t)(m0 + lr) * 512 + k0 + lc + 4);
        float4 b0 = *(const float4*)(W + (size_t)(e0 + lr) * 512 + k0 + lc);
        float4 b1 = *(const float4*)(W + (size_t)(e0 + lr) * 512 + k0 + lc + 4);
        As[lc + 0][lr] = a0.x; As[lc + 1][lr] = a0.y;
        As[lc + 2][lr] = a0.z; As[lc + 3][lr] = a0.w;
        As[lc + 4][lr] = a1.x; As[lc + 5][lr] = a1.y;
        As[lc + 6][lr] = a1.z; As[lc + 7][lr] = a1.w;
        Bs[lc + 0][lr] = b0.x; Bs[lc + 1][lr] = b0.y;
        Bs[lc + 2][lr] = b0.z; Bs[lc + 3][lr] = b0.w;
        Bs[lc + 4][lr] = b1.x; Bs[lc + 5][lr] = b1.y;
        Bs[lc + 6][lr] = b1.z; Bs[lc + 7][lr] = b1.w;
        __syncthreads();
#pragma unroll
        for (int kk = 0; kk < 16; kk++) {
            float a[8];
            *(float4*)(a)     = *(float4*)&As[kk][ty * 8];
            *(float4*)(a + 4) = *(float4*)&As[kk][ty * 8 + 4];
            ulonglong2 bA = *(ulonglong2*)&Bs[kk][tx * 8];
            ulonglong2 bB = *(ulonglong2*)&Bs[kk][tx * 8 + 4];
#pragma unroll
            for (int p = 0; p < 8; p++) {
                ull_t ap; PACK2(ap, a[p], a[p]);
                FMA2(acc2[p][0], ap, bA.x);
                FMA2(acc2[p][1], ap, bA.y);
                FMA2(acc2[p][2], ap, bB.x);
                FMA2(acc2[p][3], ap, bB.y);
            }
        }
        __syncthreads();
    }

    const int ecol = e0 + tx * 8;
    const int h = ecol >> 6;
    const int d0 = ecol & 63;
#pragma unroll
    for (int ry = 0; ry < 8; ry++) {
        const int m = m0 + ty * 8 + ry;
        const int i = m >> 4, n = m & 15;
        float o[8];
#pragma unroll
        for (int q = 0; q < 4; q++) UNPACK2(o[2*q], o[2*q+1], acc2[ry][q]);
        if (sel == 3) {
            float* dst = g_r + (size_t)m * 512 + ecol;
            *(float4*)dst       = *(float4*)&o[0];
            *(float4*)(dst + 4) = *(float4*)&o[4];
        } else {
            float* base = (sel == 0) ? g_q : (sel == 1) ? g_k : g_v;
            float* dst = base + ((size_t)(n * 8 + h) * 128 + i) * 64 + d0;
            *(float4*)dst       = *(float4*)&o[0];
            *(float4*)(dst + 4) = *(float4*)&o[4];
        }
    }
}

// ---------------- K23: merged qW GEMM (blocks 0..511) + q.k base (512..639) -
__global__ __launch_bounds__(256) void k23(const float* __restrict__ Wknow) {
    __shared__ float sm[8192];   // 32 KB, unioned
    const int t = threadIdx.x;
    const int bx = blockIdx.x;

    if (bx < 512) {
        float (*As)[128] = (float(*)[128])sm;
        float (*Bs)[128] = (float(*)[128])(sm + 16 * 128);
        const int h = bx >> 6;
        const int sub = bx & 63;
        const int m0 = (sub & 15) * 128;
        const int e0t = (sub >> 4) * 128;

        const int ty = t >> 4, tx = t & 15;
        const int lr = t >> 1;
        const int lc = (t & 1) * 8;
        const int dr = t >> 4;
        const int ec = (t & 15) * 8;

        ull_t acc2[8][4];
#pragma unroll
        for (int a = 0; a < 8; a++)
#pragma unroll
            for (int b = 0; b < 4; b++) acc2[a][b] = 0ull;

        for (int k0 = 0; k0 < 64; k0 += 16) {
            {
                const int m = m0 + lr;
                const int n = m >> 7, i = m & 127;
                const float* ar = &g_q[((size_t)(n * 8 + h) * 128 + i) * 64 + k0 + lc];
                float4 a0 = *(const float4*)ar;
                float4 a1 = *(const float4*)(ar + 4);
                As[lc + 0][lr] = a0.x; As[lc + 1][lr] = a0.y;
                As[lc + 2][lr] = a0.z; As[lc + 3][lr] = a0.w;
                As[lc + 4][lr] = a1.x; As[lc + 5][lr] = a1.y;
                As[lc + 6][lr] = a1.z; As[lc + 7][lr] = a1.w;
            }
            {
                const float* br = Wknow + (size_t)(h * 64 + k0 + dr) * 512 + e0t + ec;
                float4 b0 = *(const float4*)br;
                float4 b1 = *(const float4*)(br + 4);
                *(float4*)&Bs[dr][ec]     = b0;
                *(float4*)&Bs[dr][ec + 4] = b1;
            }
            __syncthreads();
#pragma unroll
            for (int kk = 0; kk < 16; kk++) {
                float a[8];
                *(float4*)(a)     = *(float4*)&As[kk][ty * 8];
                *(float4*)(a + 4) = *(float4*)&As[kk][ty * 8 + 4];
                ulonglong2 bA = *(ulonglong2*)&Bs[kk][tx * 8];
                ulonglong2 bB = *(ulonglong2*)&Bs[kk][tx * 8 + 4];
#pragma unroll
                for (int p = 0; p < 8; p++) {
                    ull_t ap; PACK2(ap, a[p], a[p]);
                    FMA2(acc2[p][0], ap, bA.x);
                    FMA2(acc2[p][1], ap, bA.y);
                    FMA2(acc2[p][2], ap, bB.x);
                    FMA2(acc2[p][3], ap, bB.y);
                }
            }
            __syncthreads();
        }
#pragma unroll
        for (int ry = 0; ry < 8; ry++) {
            const int m = m0 + ty * 8 + ry;
            const int n = m >> 7, i = m & 127;
            float o[8];
#pragma unroll
            for (int q = 0; q < 4; q++) UNPACK2(o[2*q], o[2*q+1], acc2[ry][q]);
            float* dst = &g_qW[((size_t)(n * 8 + h) * 128 + i) * 512 + e0t + tx * 8];
            *(float4*)dst       = *(float4*)&o[0];
            *(float4*)(dst + 4) = *(float4*)&o[4];
        }
    } else {
        float (*qT)[128] = (float(*)[128])sm;
        float (*kT)[128] = (float(*)[128])(sm + 32 * 128);
        const int b = bx - 512;
        const int ty = t >> 4, tx = t & 15;

        float acc[8][8];
#pragma unroll
        for (int p = 0; p < 8; p++)
#pragma unroll
            for (int q = 0; q < 8; q++) acc[p][q] = 0.f;

        for (int d0 = 0; d0 < 64; d0 += 32) {
#pragma unroll
            for (int u = 0; u < 4; u++) {
                int ii = (t >> 3) + 32 * u;
                int d4 = (t & 7) * 4;
                float4 a = *(const float4*)&g_q[((size_t)b * 128 + ii) * 64 + d0 + d4];
                qT[d4 + 0][ii] = a.x; qT[d4 + 1][ii] = a.y;
                qT[d4 + 2][ii] = a.z; qT[d4 + 3][ii] = a.w;
                float4 bb = *(const float4*)&g_k[((size_t)b * 128 + ii) * 64 + d0 + d4];
                kT[d4 + 0][ii] = bb.x; kT[d4 + 1][ii] = bb.y;
                kT[d4 + 2][ii] = bb.z; kT[d4 + 3][ii] = bb.w;
            }
            __syncthreads();
#pragma unroll
            for (int d = 0; d < 32; d++) {
                float a[8], bl[8];
                *(float4*)(a)      = *(float4*)&qT[d][ty * 8];
                *(float4*)(a + 4)  = *(float4*)&qT[d][ty * 8 + 4];
                *(float4*)(bl)     = *(float4*)&kT[d][tx * 8];
                *(float4*)(bl + 4) = *(float4*)&kT[d][tx * 8 + 4];
#pragma unroll
                for (int p = 0; p < 8; p++)
#pragma unroll
                    for (int q = 0; q < 8; q++) acc[p][q] += a[p] * bl[q];
            }
            __syncthreads();
        }
#pragma unroll
        for (int p = 0; p < 8; p++) {
            float* dst = &g_aw[((size_t)b * 128 + ty * 8 + p) * 128 + tx * 8];
            *(float4*)dst       = *(float4*)&acc[p][0];
            *(float4*)(dst + 4) = *(float4*)&acc[p][4];
        }
    }
}

// ---------------- K34: ONE-PASS logits + exp + s-accum over know ------------
// Round-7 structure, but phase-1 warp = (2 heads x 8 j-rows): qw regs 64->32,
// butterfly 6->5 shfl. __launch_bounds__(256,3) -> 3 blocks/SM (24 warps).
#define TJ 16
__global__ __launch_bounds__(256, 3) void k34_onepass(const float* __restrict__ know,
                                                      const int* __restrict__ mask) {
    __shared__ float kn_s[2][TJ][512];   // 64 KB (double buffer)
    __shared__ ull_t pT2[TJ][8];         // 1 KB  (packed (p,p))
    __shared__ float pq_s[8][128];       // 4 KB  (qk base -> unnormalized p)
    __shared__ unsigned char m8[8][128]; // 1 KB
    __shared__ float inv_s[8];

    const int n = blockIdx.x >> 7;
    const int i = blockIdx.x & 127;
    const int t = threadIdx.x, w = t >> 5, l = t & 31;
    const int hg = w & 3, jq = w >> 2;           // phase-1 warp role: 2 heads, 8 j
    const int h0 = hg * 2;
    const int g = t >> 7;                        // phase-3 h-group (0/1)
    const int e0 = (t & 127) << 2;               // phase-3 e-chunk

    // ---- preload q.k base (into pq_s) + mask ----
    {
        int h = t >> 5, j0 = (t & 31) << 2;
        *(float4*)&pq_s[h][j0] =
            *(const float4*)&g_aw[(((size_t)(n * 8 + h) * 128 + i)) * 128 + j0];
        int4 mm = *(const int4*)&mask[(((size_t)(n * 8 + h) * 128 + i)) * 128 + j0];
        uchar4 mb;
        mb.x = (unsigned char)(mm.x != 0); mb.y = (unsigned char)(mm.y != 0);
        mb.z = (unsigned char)(mm.z != 0); mb.w = (unsigned char)(mm.w != 0);
        *(uchar4*)&m8[h][j0] = mb;
    }

    // ---- qW slices into registers: 2 heads x full 512e, e = 4l + 128u ----
    ulonglong2 qw[2][4];
#pragma unroll
    for (int h = 0; h < 2; h++) {
        const float* qb = &g_qW[(((size_t)(n * 8 + h0 + h) * 128 + i)) * 512 + 4 * l];
#pragma unroll
        for (int u = 0; u < 4; u++)
            qw[h][u] = *(const ulonglong2*)(qb + 128 * u);
    }

    const float* knbase = know + ((size_t)n * 16384 + (size_t)i * 128) * 512;
    const uint32_t kn_sa = (uint32_t)__cvta_generic_to_shared(&kn_s[0][0][0]);

    ull_t accv[4][2];
#pragma unroll
    for (int hh = 0; hh < 4; hh++) { accv[hh][0] = 0ull; accv[hh][1] = 0ull; }

    // ---- prologue: stage tile 0 into buf 0 via cp.async ----
#pragma unroll
    for (int u = 0; u < 8; u++) {
        int c = t + 256 * u;
        int r = c >> 7, ch = c & 127;
        cpa16(kn_sa + (uint32_t)(r * 2048 + ch * 16),
              knbase + (size_t)r * 512 + ch * 4);
    }
    cpa_commit();

    int buf = 0;
#pragma unroll 1
    for (int tt = 0; tt < 8; tt++) {
        cpa_wait_all();
        __syncthreads();   // tile[buf] visible; prev phase3 done with pT2

        if (tt < 7) {
            const float* nb = knbase + (size_t)(tt + 1) * TJ * 512;
            const uint32_t sb = kn_sa + (uint32_t)((buf ^ 1) * TJ * 2048);
#pragma unroll
            for (int u = 0; u < 8; u++) {
                int c = t + 256 * u;
                int r = c >> 7, ch = c & 127;
                cpa16(sb + (uint32_t)(r * 2048 + ch * 16),
                      nb + (size_t)r * 512 + ch * 4);
            }
            cpa_commit();
        }

        // ---- phase 1: full logits, inline exp; warp does 8 j rows, 2 heads --
#pragma unroll
        for (int jj = 0; jj < 8; jj++) {
            const int jl = jq * 8 + jj;
            const int j = tt * TJ + jl;
            ulonglong2 kv[4];
#pragma unroll
            for (int u = 0; u < 4; u++)
                kv[u] = *(const ulonglong2*)&kn_s[buf][jl][4 * l + 128 * u];
            ull_t a2[2];
            a2[0] = 0ull; a2[1] = 0ull;
#pragma unroll
            for (int h = 0; h < 2; h++)
#pragma unroll
                for (int u = 0; u < 4; u++) {
                    FMA2(a2[h], kv[u].x, qw[h][u].x);
                    FMA2(a2[h], kv[u].y, qw[h][u].y);
                }
            float v0, v1;
            {
                float lo, hi;
                UNPACK2(lo, hi, a2[0]); v0 = lo + hi;
                UNPACK2(lo, hi, a2[1]); v1 = lo + hi;
            }
            // value-halving butterfly: 2 vals over 32 lanes (5 shfl)
            {
                float give = (l & 16) ? v0 : v1;
                float keep = (l & 16) ? v1 : v0;
                v0 = keep + __shfl_xor_sync(0xffffffffu, give, 16);
            }
            v0 += __shfl_xor_sync(0xffffffffu, v0, 8);
            v0 += __shfl_xor_sync(0xffffffffu, v0, 4);
            v0 += __shfl_xor_sync(0xffffffffu, v0, 2);
            v0 += __shfl_xor_sync(0xffffffffu, v0, 1);
            if ((l & 15) == 0) {
                const int h = h0 + (l >> 4);
                float lg = (v0 + pq_s[h][j]) * SCALING;
                float p = m8[h][j] ? __expf(lg) : 0.f;
                pq_s[h][j] = p;
                ull_t p2; PACK2(p2, p, p);
                pT2[jl][h] = p2;
            }
        }
        __syncthreads();   // p ready

        // ---- phase 3: s accumulation from same tile ----
        {
            const int h0p = g * 4;
#pragma unroll
            for (int jl = 0; jl < TJ; jl++) {
                ulonglong2 kv = *(const ulonglong2*)&kn_s[buf][jl][e0];
                ulonglong2 pa = *(const ulonglong2*)&pT2[jl][h0p];
                ulonglong2 pb = *(const ulonglong2*)&pT2[jl][h0p + 2];
                FMA2(accv[0][0], pa.x, kv.x); FMA2(accv[0][1], pa.x, kv.y);
                FMA2(accv[1][0], pa.y, kv.x); FMA2(accv[1][1], pa.y, kv.y);
                FMA2(accv[2][0], pb.x, kv.x); FMA2(accv[2][1], pb.x, kv.y);
                FMA2(accv[3][0], pb.y, kv.x); FMA2(accv[3][1], pb.y, kv.y);
            }
        }
        buf ^= 1;
    }

    // ---- normalization: warp w sums p over head w ----
    {
        float s = 0.f;
#pragma unroll
        for (int c = 0; c < 4; c++) s += pq_s[w][l + 32 * c];
#pragma unroll
        for (int off = 16; off; off >>= 1)
            s += __shfl_xor_sync(0xffffffffu, s, off);
        if (l == 0) inv_s[w] = 1.f / s;
    }
    __syncthreads();

    // ---- write s (normalized) ----
    {
        const int h0p = g * 4;
#pragma unroll
        for (int hh = 0; hh < 4; hh++) {
            float inv = inv_s[h0p + hh];
            float4 o;
            UNPACK2(o.x, o.y, accv[hh][0]);
            UNPACK2(o.z, o.w, accv[hh][1]);
            o.x *= inv; o.y *= inv; o.z *= inv; o.w *= inv;
            *(float4*)&g_s[(((size_t)(n * 8 + h0p + hh) * 128 + i)) * 512 + e0] = o;
        }
    }
    // ---- write normalized aw ----
#pragma unroll
    for (int u = 0; u < 4; u++) {
        int c = t + 256 * u;
        int h = c >> 7, j = c & 127;
        g_aw[(((size_t)(n * 8 + h) * 128 + i)) * 128 + j] = pq_s[h][j] * inv_s[h];
    }
}

// ---------------- K4b: attn GEMM, reg-double-buffered (1 bar/step) ----------
// (round-10 measured version: 43.1us)
__global__ __launch_bounds__(256) void k4b_attn(const float* __restrict__ Wknow) {
    __shared__ float As[2][32][128];
    __shared__ float Bs[2][32][64];
    const int n = blockIdx.x;
    const int h = blockIdx.y;
    const int t = threadIdx.x;
    const int ty = t >> 4, tx = t & 15;
    const int rr = t >> 1;            // A row
    const int kq = (t & 1) * 16;      // A col chunk

    const size_t bhrow = ((size_t)(n * 8 + h)) * 128;

    float4 pa[4], pb[2];
    auto gload = [&](int k0) {
        const float* p = (k0 < 128)
            ? &g_aw[(bhrow + rr) * 128 + k0 + kq]
            : &g_s[(bhrow + rr) * 512 + (k0 - 128) + kq];
        pa[0] = *(const float4*)p;
        pa[1] = *(const float4*)(p + 4);
        pa[2] = *(const float4*)(p + 8);
        pa[3] = *(const float4*)(p + 12);
        if (k0 < 128) {
            const int kr = t >> 3, dq = (t & 7) * 8;
            const float* q = &g_v[(bhrow + (k0 + kr)) * 64 + dq];
            pb[0] = *(const float4*)q;
            pb[1] = *(const float4*)(q + 4);
        } else {
            const int d = t >> 2, eq = (t & 3) * 8;
            const float* q = Wknow + (size_t)(h * 64 + d) * 512 + (k0 - 128) + eq;
            pb[0] = *(const float4*)q;
            pb[1] = *(const float4*)(q + 4);
        }
    };
    auto sstore = [&](int k0, int bf) {
#pragma unroll
        for (int c = 0; c < 4; c++) {
            As[bf][kq + 4 * c + 0][rr] = pa[c].x;
            As[bf][kq + 4 * c + 1][rr] = pa[c].y;
            As[bf][kq + 4 * c + 2][rr] = pa[c].z;
            As[bf][kq + 4 * c + 3][rr] = pa[c].w;
        }
        if (k0 < 128) {
            const int kr = t >> 3, dq = (t & 7) * 8;
            *(float4*)&Bs[bf][kr][dq]     = pb[0];
            *(float4*)&Bs[bf][kr][dq + 4] = pb[1];
        } else {
            const int d = t >> 2, eq = (t & 3) * 8;
            Bs[bf][eq + 0][d] = pb[0].x; Bs[bf][eq + 1][d] = pb[0].y;
            Bs[bf][eq + 2][d] = pb[0].z; Bs[bf][eq + 3][d] = pb[0].w;
            Bs[bf][eq + 4][d] = pb[1].x; Bs[bf][eq + 5][d] = pb[1].y;
            Bs[bf][eq + 6][d] = pb[1].z; Bs[bf][eq + 7][d] = pb[1].w;
        }
    };

    ull_t acc2[8][2];
#pragma unroll
    for (int a = 0; a < 8; a++) { acc2[a][0] = 0ull; acc2[a][1] = 0ull; }

    gload(0); sstore(0, 0); __syncthreads();
    int buf = 0;
#pragma unroll 1
    for (int k0 = 0; k0 < 640; k0 += 32) {
        if (k0 < 608) gload(k0 + 32);
#pragma unroll
        for (int kk = 0; kk < 32; kk++) {
            float a[8];
            *(float4*)(a)     = *(float4*)&As[buf][kk][ty * 8];
            *(float4*)(a + 4) = *(float4*)&As[buf][kk][ty * 8 + 4];
            ulonglong2 b2 = *(ulonglong2*)&Bs[buf][kk][tx * 4];
#pragma unroll
            for (int p = 0; p < 8; p++) {
                ull_t ap; PACK2(ap, a[p], a[p]);
                FMA2(acc2[p][0], ap, b2.x);
                FMA2(acc2[p][1], ap, b2.y);
            }
        }
        if (k0 < 608) sstore(k0 + 32, buf ^ 1);
        __syncthreads();
        buf ^= 1;
    }
#pragma unroll
    for (int ry = 0; ry < 8; ry++) {
        const int i = ty * 8 + ry;
        float4 o;
        UNPACK2(o.x, o.y, acc2[ry][0]);
        UNPACK2(o.z, o.w, acc2[ry][1]);
        float* dst = g_attn + ((size_t)i * 16 + n) * 512 + h * 64 + tx * 4;
        *(float4*)dst = o;
    }
}

// ---------------- K5: gating  out = g*r + (1-g)*attn ------------------------
__global__ __launch_bounds__(128) void k5_gate(const float* __restrict__ Wbeta,
                                               float* __restrict__ out) {
    const int m = blockIdx.x;
    const int t = threadIdx.x;
    const int w = t >> 5, l = t & 31;
    __shared__ float red[4];

    const float* a = g_attn + (size_t)m * 512;
    const float* r = g_r + (size_t)m * 512;

    float z = 0.f;
#pragma unroll
    for (int c = 0; c < 4; c++) {
        int e = t + 128 * c;
        float av = a[e], rv = r[e];
        z += Wbeta[e] * av + Wbeta[512 + e] * rv + Wbeta[1024 + e] * (av - rv);
    }
#pragma unroll
    for (int off = 16; off; off >>= 1)
        z += __shfl_xor_sync(0xffffffffu, z, off);
    if (l == 0) red[w] = z;
    __syncthreads();
    float zt = red[0] + red[1] + red[2] + red[3];
    float g = 1.f / (1.f + __expf(-zt));

#pragma unroll
    for (int c = 0; c < 4; c++) {
        int e = t + 128 * c;
        out[(size_t)m * 512 + e] = g * r[e] + (1.f - g) * a[e];
    }
}

// ---------------- launch -----------------------------------------------------
extern "C" void kernel_launch(void* const* d_in, const int* in_sizes, int n_in,
                              void* d_out, int out_size) {
    const float* x     = (const float*)d_in[0];
    const float* know  = (const float*)d_in[1];
    const int*   mask  = (const int*)d_in[2];
    const float* Wq    = (const float*)d_in[3];
    const float* Wk    = (const float*)d_in[4];
    const float* Wv    = (const float*)d_in[5];
    const float* Wknow = (const float*)d_in[6];
    const float* Wskip = (const float*)d_in[7];
    const float* Wbeta = (const float*)d_in[8];
    float* out = (float*)d_out;

    k1_proj<<<dim3(16, 16), 256>>>(x, Wq, Wk, Wv, Wskip);
    k23<<<640, 256>>>(Wknow);
    k34_onepass<<<2048, 256>>>(know, mask);
    k4b_attn<<<dim3(16, 8), 256>>>(Wknow);
    k5_gate<<<2048, 128>>>(Wbeta, out);
}

// round 13
// speedup vs baseline: 1.0756x; 1.0756x over previous
#include <cuda_runtime.h>
#include <cstdint>

#define SLEN 128
#define BSZ  16
#define EMB  512
#define NHEAD 8
#define HDIM 64
#define BH   (BSZ*NHEAD)   // 128
#define NEG_INF (-1e9f)
#define SCALING 0.125f     // 1/sqrt(64)

// ---- f32x2 packed math (Blackwell) ----
#define FMA2(d, a, b) asm("fma.rn.f32x2 %0, %1, %2, %0;" : "+l"(d) : "l"(a), "l"(b))
#define PACK2(u, lo, hi) asm("mov.b64 %0, {%1, %2};" : "=l"(u) : "f"(lo), "f"(hi))
#define UNPACK2(lo, hi, u) asm("mov.b64 {%0, %1}, %2;" : "=f"(lo), "=f"(hi) : "l"(u))

typedef unsigned long long ull_t;

__device__ __forceinline__ void cpa16(uint32_t saddr, const void* gaddr) {
    asm volatile("cp.async.ca.shared.global [%0], [%1], 16;" :: "r"(saddr), "l"(gaddr));
}
__device__ __forceinline__ void cpa_commit() {
    asm volatile("cp.async.commit_group;");
}
__device__ __forceinline__ void cpa_wait_all() {
    asm volatile("cp.async.wait_group 0;");
}

// ---------------- scratch (device globals; no runtime alloc) ----------------
__device__ float g_q[BH*SLEN*HDIM];        // [b][i][d]
__device__ float g_k[BH*SLEN*HDIM];        // [b][j][d]
__device__ float g_v[BH*SLEN*HDIM];        // [b][j][d]
__device__ float g_r[SLEN*BSZ*EMB];        // [m][e]
__device__ float g_qW[BH*SLEN*EMB];        // [b][i][e]
__device__ float g_aw[BH*SLEN*SLEN];       // [b][i][j]  (qk base, then normalized aw)
__device__ float g_s[BH*SLEN*EMB];         // [b][i][e]
__device__ float g_attn[SLEN*BSZ*EMB];     // [m][e]

// ---------------- K1: fused projections  C = X(2048x512) @ W^T --------------
// A stored in smem PRE-DUPLICATED as {a,a} ull pairs: zero packs in MMA loop.
__global__ __launch_bounds__(256) void k1_proj(const float* __restrict__ x,
                                               const float* __restrict__ Wq,
                                               const float* __restrict__ Wk,
                                               const float* __restrict__ Wv,
                                               const float* __restrict__ Wskip) {
    __shared__ ull_t As2[16][128];   // 16 KB: {a,a} per (kk,row)
    __shared__ float Bs[16][128];    // 8 KB
    const int m0 = blockIdx.y * 128;
    const int c0 = blockIdx.x * 128;
    const int sel = c0 >> 9;
    const float* W = (sel == 0) ? Wq : (sel == 1) ? Wk : (sel == 2) ? Wv : Wskip;
    const int e0 = c0 & 511;

    const int t  = threadIdx.x;
    const int ty = t >> 4, tx = t & 15;
    const int lr = t >> 1;
    const int lc = (t & 1) * 8;

    ull_t acc2[8][4];
#pragma unroll
    for (int a = 0; a < 8; a++)
#pragma unroll
        for (int b = 0; b < 4; b++) acc2[a][b] = 0ull;

    for (int k0 = 0; k0 < 512; k0 += 16) {
        float4 a0 = *(const float4*)(x + (size_t)(m0 + lr) * 512 + k0 + lc);
        float4 a1 = *(const float4*)(x + (size_t)(m0 + lr) * 512 + k0 + lc + 4);
        float4 b0 = *(const float4*)(W + (size_t)(e0 + lr) * 512 + k0 + lc);
        float4 b1 = *(const float4*)(W + (size_t)(e0 + lr) * 512 + k0 + lc + 4);
        {
            ull_t d;
            PACK2(d, a0.x, a0.x); As2[lc + 0][lr] = d;
            PACK2(d, a0.y, a0.y); As2[lc + 1][lr] = d;
            PACK2(d, a0.z, a0.z); As2[lc + 2][lr] = d;
            PACK2(d, a0.w, a0.w); As2[lc + 3][lr] = d;
            PACK2(d, a1.x, a1.x); As2[lc + 4][lr] = d;
            PACK2(d, a1.y, a1.y); As2[lc + 5][lr] = d;
            PACK2(d, a1.z, a1.z); As2[lc + 6][lr] = d;
            PACK2(d, a1.w, a1.w); As2[lc + 7][lr] = d;
        }
        Bs[lc + 0][lr] = b0.x; Bs[lc + 1][lr] = b0.y;
        Bs[lc + 2][lr] = b0.z; Bs[lc + 3][lr] = b0.w;
        Bs[lc + 4][lr] = b1.x; Bs[lc + 5][lr] = b1.y;
        Bs[lc + 6][lr] = b1.z; Bs[lc + 7][lr] = b1.w;
        __syncthreads();
#pragma unroll
        for (int kk = 0; kk < 16; kk++) {
            ulonglong2 aA = *(ulonglong2*)&As2[kk][ty * 8];
            ulonglong2 aB = *(ulonglong2*)&As2[kk][ty * 8 + 2];
            ulonglong2 aC = *(ulonglong2*)&As2[kk][ty * 8 + 4];
            ulonglong2 aD = *(ulonglong2*)&As2[kk][ty * 8 + 6];
            ulonglong2 bA = *(ulonglong2*)&Bs[kk][tx * 8];
            ulonglong2 bB = *(ulonglong2*)&Bs[kk][tx * 8 + 4];
            FMA2(acc2[0][0], aA.x, bA.x); FMA2(acc2[0][1], aA.x, bA.y);
            FMA2(acc2[0][2], aA.x, bB.x); FMA2(acc2[0][3], aA.x, bB.y);
            FMA2(acc2[1][0], aA.y, bA.x); FMA2(acc2[1][1], aA.y, bA.y);
            FMA2(acc2[1][2], aA.y, bB.x); FMA2(acc2[1][3], aA.y, bB.y);
            FMA2(acc2[2][0], aB.x, bA.x); FMA2(acc2[2][1], aB.x, bA.y);
            FMA2(acc2[2][2], aB.x, bB.x); FMA2(acc2[2][3], aB.x, bB.y);
            FMA2(acc2[3][0], aB.y, bA.x); FMA2(acc2[3][1], aB.y, bA.y);
            FMA2(acc2[3][2], aB.y, bB.x); FMA2(acc2[3][3], aB.y, bB.y);
            FMA2(acc2[4][0], aC.x, bA.x); FMA2(acc2[4][1], aC.x, bA.y);
            FMA2(acc2[4][2], aC.x, bB.x); FMA2(acc2[4][3], aC.x, bB.y);
            FMA2(acc2[5][0], aC.y, bA.x); FMA2(acc2[5][1], aC.y, bA.y);
            FMA2(acc2[5][2], aC.y, bB.x); FMA2(acc2[5][3], aC.y, bB.y);
            FMA2(acc2[6][0], aD.x, bA.x); FMA2(acc2[6][1], aD.x, bA.y);
            FMA2(acc2[6][2], aD.x, bB.x); FMA2(acc2[6][3], aD.x, bB.y);
            FMA2(acc2[7][0], aD.y, bA.x); FMA2(acc2[7][1], aD.y, bA.y);
            FMA2(acc2[7][2], aD.y, bB.x); FMA2(acc2[7][3], aD.y, bB.y);
        }
        __syncthreads();
    }

    const int ecol = e0 + tx * 8;
    const int h = ecol >> 6;
    const int d0 = ecol & 63;
#pragma unroll
    for (int ry = 0; ry < 8; ry++) {
        const int m = m0 + ty * 8 + ry;
        const int i = m >> 4, n = m & 15;
        float o[8];
#pragma unroll
        for (int q = 0; q < 4; q++) UNPACK2(o[2*q], o[2*q+1], acc2[ry][q]);
        if (sel == 3) {
            float* dst = g_r + (size_t)m * 512 + ecol;
            *(float4*)dst       = *(float4*)&o[0];
            *(float4*)(dst + 4) = *(float4*)&o[4];
        } else {
            float* base = (sel == 0) ? g_q : (sel == 1) ? g_k : g_v;
            float* dst = base + ((size_t)(n * 8 + h) * 128 + i) * 64 + d0;
            *(float4*)dst       = *(float4*)&o[0];
            *(float4*)(dst + 4) = *(float4*)&o[4];
        }
    }
}

// ---------------- K23: merged qW GEMM (blocks 0..511) + q.k base (512..639) -
__global__ __launch_bounds__(256) void k23(const float* __restrict__ Wknow) {
    __shared__ float sm[8192];   // 32 KB, unioned
    const int t = threadIdx.x;
    const int bx = blockIdx.x;

    if (bx < 512) {
        float (*As)[128] = (float(*)[128])sm;
        float (*Bs)[128] = (float(*)[128])(sm + 16 * 128);
        const int h = bx >> 6;
        const int sub = bx & 63;
        const int m0 = (sub & 15) * 128;
        const int e0t = (sub >> 4) * 128;

        const int ty = t >> 4, tx = t & 15;
        const int lr = t >> 1;
        const int lc = (t & 1) * 8;
        const int dr = t >> 4;
        const int ec = (t & 15) * 8;

        ull_t acc2[8][4];
#pragma unroll
        for (int a = 0; a < 8; a++)
#pragma unroll
            for (int b = 0; b < 4; b++) acc2[a][b] = 0ull;

        for (int k0 = 0; k0 < 64; k0 += 16) {
            {
                const int m = m0 + lr;
                const int n = m >> 7, i = m & 127;
                const float* ar = &g_q[((size_t)(n * 8 + h) * 128 + i) * 64 + k0 + lc];
                float4 a0 = *(const float4*)ar;
                float4 a1 = *(const float4*)(ar + 4);
                As[lc + 0][lr] = a0.x; As[lc + 1][lr] = a0.y;
                As[lc + 2][lr] = a0.z; As[lc + 3][lr] = a0.w;
                As[lc + 4][lr] = a1.x; As[lc + 5][lr] = a1.y;
                As[lc + 6][lr] = a1.z; As[lc + 7][lr] = a1.w;
            }
            {
                const float* br = Wknow + (size_t)(h * 64 + k0 + dr) * 512 + e0t + ec;
                float4 b0 = *(const float4*)br;
                float4 b1 = *(const float4*)(br + 4);
                *(float4*)&Bs[dr][ec]     = b0;
                *(float4*)&Bs[dr][ec + 4] = b1;
            }
            __syncthreads();
#pragma unroll
            for (int kk = 0; kk < 16; kk++) {
                float a[8];
                *(float4*)(a)     = *(float4*)&As[kk][ty * 8];
                *(float4*)(a + 4) = *(float4*)&As[kk][ty * 8 + 4];
                ulonglong2 bA = *(ulonglong2*)&Bs[kk][tx * 8];
                ulonglong2 bB = *(ulonglong2*)&Bs[kk][tx * 8 + 4];
#pragma unroll
                for (int p = 0; p < 8; p++) {
                    ull_t ap; PACK2(ap, a[p], a[p]);
                    FMA2(acc2[p][0], ap, bA.x);
                    FMA2(acc2[p][1], ap, bA.y);
                    FMA2(acc2[p][2], ap, bB.x);
                    FMA2(acc2[p][3], ap, bB.y);
                }
            }
            __syncthreads();
        }
#pragma unroll
        for (int ry = 0; ry < 8; ry++) {
            const int m = m0 + ty * 8 + ry;
            const int n = m >> 7, i = m & 127;
            float o[8];
#pragma unroll
            for (int q = 0; q < 4; q++) UNPACK2(o[2*q], o[2*q+1], acc2[ry][q]);
            float* dst = &g_qW[((size_t)(n * 8 + h) * 128 + i) * 512 + e0t + tx * 8];
            *(float4*)dst       = *(float4*)&o[0];
            *(float4*)(dst + 4) = *(float4*)&o[4];
        }
    } else {
        float (*qT)[128] = (float(*)[128])sm;
        float (*kT)[128] = (float(*)[128])(sm + 32 * 128);
        const int b = bx - 512;
        const int ty = t >> 4, tx = t & 15;

        float acc[8][8];
#pragma unroll
        for (int p = 0; p < 8; p++)
#pragma unroll
            for (int q = 0; q < 8; q++) acc[p][q] = 0.f;

        for (int d0 = 0; d0 < 64; d0 += 32) {
#pragma unroll
            for (int u = 0; u < 4; u++) {
                int ii = (t >> 3) + 32 * u;
                int d4 = (t & 7) * 4;
                float4 a = *(const float4*)&g_q[((size_t)b * 128 + ii) * 64 + d0 + d4];
                qT[d4 + 0][ii] = a.x; qT[d4 + 1][ii] = a.y;
                qT[d4 + 2][ii] = a.z; qT[d4 + 3][ii] = a.w;
                float4 bb = *(const float4*)&g_k[((size_t)b * 128 + ii) * 64 + d0 + d4];
                kT[d4 + 0][ii] = bb.x; kT[d4 + 1][ii] = bb.y;
                kT[d4 + 2][ii] = bb.z; kT[d4 + 3][ii] = bb.w;
            }
            __syncthreads();
#pragma unroll
            for (int d = 0; d < 32; d++) {
                float a[8], bl[8];
                *(float4*)(a)      = *(float4*)&qT[d][ty * 8];
                *(float4*)(a + 4)  = *(float4*)&qT[d][ty * 8 + 4];
                *(float4*)(bl)     = *(float4*)&kT[d][tx * 8];
                *(float4*)(bl + 4) = *(float4*)&kT[d][tx * 8 + 4];
#pragma unroll
                for (int p = 0; p < 8; p++)
#pragma unroll
                    for (int q = 0; q < 8; q++) acc[p][q] += a[p] * bl[q];
            }
            __syncthreads();
        }
#pragma unroll
        for (int p = 0; p < 8; p++) {
            float* dst = &g_aw[((size_t)b * 128 + ty * 8 + p) * 128 + tx * 8];
            *(float4*)dst       = *(float4*)&acc[p][0];
            *(float4*)(dst + 4) = *(float4*)&acc[p][4];
        }
    }
}

// ---------------- K34: ONE-PASS logits + exp + s-accum over know ------------
// (round-7/11 version: best measured, DO NOT RESTRUCTURE)
#define TJ 16
__global__ __launch_bounds__(256, 2) void k34_onepass(const float* __restrict__ know,
                                                      const int* __restrict__ mask) {
    __shared__ float kn_s[2][TJ][512];   // 64 KB (double buffer)
    __shared__ ull_t pT2[TJ][8];         // 1 KB  (packed (p,p))
    __shared__ float pq_s[8][128];       // 4 KB  (qk base -> unnormalized p)
    __shared__ unsigned char m8[8][128]; // 1 KB
    __shared__ float inv_s[8];

    const int n = blockIdx.x >> 7;
    const int i = blockIdx.x & 127;
    const int t = threadIdx.x, w = t >> 5, l = t & 31;
    const int hg = w & 1, jq = w >> 1;           // phase-1 warp role
    const int h0 = hg * 4;
    const int g = t >> 7;                        // phase-3 h-group (0/1)
    const int e0 = (t & 127) << 2;               // phase-3 e-chunk

    // ---- preload q.k base (into pq_s) + mask ----
    {
        int h = t >> 5, j0 = (t & 31) << 2;
        *(float4*)&pq_s[h][j0] =
            *(const float4*)&g_aw[(((size_t)(n * 8 + h) * 128 + i)) * 128 + j0];
        int4 mm = *(const int4*)&mask[(((size_t)(n * 8 + h) * 128 + i)) * 128 + j0];
        uchar4 mb;
        mb.x = (unsigned char)(mm.x != 0); mb.y = (unsigned char)(mm.y != 0);
        mb.z = (unsigned char)(mm.z != 0); mb.w = (unsigned char)(mm.w != 0);
        *(uchar4*)&m8[h][j0] = mb;
    }

    // ---- qW slices into registers: 4 heads x full 512e, e = 4l + 128u ----
    ulonglong2 qw[4][4];
#pragma unroll
    for (int h = 0; h < 4; h++) {
        const float* qb = &g_qW[(((size_t)(n * 8 + h0 + h) * 128 + i)) * 512 + 4 * l];
#pragma unroll
        for (int u = 0; u < 4; u++)
            qw[h][u] = *(const ulonglong2*)(qb + 128 * u);
    }

    const float* knbase = know + ((size_t)n * 16384 + (size_t)i * 128) * 512;
    const uint32_t kn_sa = (uint32_t)__cvta_generic_to_shared(&kn_s[0][0][0]);

    ull_t accv[4][2];
#pragma unroll
    for (int hh = 0; hh < 4; hh++) { accv[hh][0] = 0ull; accv[hh][1] = 0ull; }

    // ---- prologue: stage tile 0 into buf 0 via cp.async ----
#pragma unroll
    for (int u = 0; u < 8; u++) {
        int c = t + 256 * u;
        int r = c >> 7, ch = c & 127;
        cpa16(kn_sa + (uint32_t)(r * 2048 + ch * 16),
              knbase + (size_t)r * 512 + ch * 4);
    }
    cpa_commit();

    int buf = 0;
#pragma unroll 1
    for (int tt = 0; tt < 8; tt++) {
        cpa_wait_all();
        __syncthreads();   // tile[buf] visible; prev phase3 done with pT2

        if (tt < 7) {
            const float* nb = knbase + (size_t)(tt + 1) * TJ * 512;
            const uint32_t sb = kn_sa + (uint32_t)((buf ^ 1) * TJ * 2048);
#pragma unroll
            for (int u = 0; u < 8; u++) {
                int c = t + 256 * u;
                int r = c >> 7, ch = c & 127;
                cpa16(sb + (uint32_t)(r * 2048 + ch * 16),
                      nb + (size_t)r * 512 + ch * 4);
            }
            cpa_commit();
        }

        // ---- phase 1: full logits, inline exp; warp does 4 j rows ----
#pragma unroll
        for (int jj = 0; jj < 4; jj++) {
            const int jl = jq * 4 + jj;
            const int j = tt * TJ + jl;
            ulonglong2 kv[4];
#pragma unroll
            for (int u = 0; u < 4; u++)
                kv[u] = *(const ulonglong2*)&kn_s[buf][jl][4 * l + 128 * u];
            ull_t a2[4];
#pragma unroll
            for (int h = 0; h < 4; h++) a2[h] = 0ull;
#pragma unroll
            for (int h = 0; h < 4; h++)
#pragma unroll
                for (int u = 0; u < 4; u++) {
                    FMA2(a2[h], kv[u].x, qw[h][u].x);
                    FMA2(a2[h], kv[u].y, qw[h][u].y);
                }
            float v[4];
#pragma unroll
            for (int h = 0; h < 4; h++) {
                float lo, hi; UNPACK2(lo, hi, a2[h]); v[h] = lo + hi;
            }
#pragma unroll
            for (int h = 0; h < 2; h++) {
                float give = (l & 16) ? v[h] : v[h + 2];
                float keep = (l & 16) ? v[h + 2] : v[h];
                v[h] = keep + __shfl_xor_sync(0xffffffffu, give, 16);
            }
            {
                float give = (l & 8) ? v[0] : v[1];
                float keep = (l & 8) ? v[1] : v[0];
                v[0] = keep + __shfl_xor_sync(0xffffffffu, give, 8);
            }
            v[0] += __shfl_xor_sync(0xffffffffu, v[0], 4);
            v[0] += __shfl_xor_sync(0xffffffffu, v[0], 2);
            v[0] += __shfl_xor_sync(0xffffffffu, v[0], 1);
            if ((l & 7) == 0) {
                const int h = h0 + ((l >> 4) & 1) * 2 + ((l >> 3) & 1);
                float lg = (v[0] + pq_s[h][j]) * SCALING;
                float p = m8[h][j] ? __expf(lg) : 0.f;
                pq_s[h][j] = p;
                ull_t p2; PACK2(p2, p, p);
                pT2[jl][h] = p2;
            }
        }
        __syncthreads();   // p ready

        // ---- phase 3: s accumulation from same tile ----
        {
            const int h0p = g * 4;
#pragma unroll
            for (int jl = 0; jl < TJ; jl++) {
                ulonglong2 kv = *(const ulonglong2*)&kn_s[buf][jl][e0];
                ulonglong2 pa = *(const ulonglong2*)&pT2[jl][h0p];
                ulonglong2 pb = *(const ulonglong2*)&pT2[jl][h0p + 2];
                FMA2(accv[0][0], pa.x, kv.x); FMA2(accv[0][1], pa.x, kv.y);
                FMA2(accv[1][0], pa.y, kv.x); FMA2(accv[1][1], pa.y, kv.y);
                FMA2(accv[2][0], pb.x, kv.x); FMA2(accv[2][1], pb.x, kv.y);
                FMA2(accv[3][0], pb.y, kv.x); FMA2(accv[3][1], pb.y, kv.y);
            }
        }
        buf ^= 1;
    }

    // ---- normalization: warp w sums p over head w ----
    {
        float s = 0.f;
#pragma unroll
        for (int c = 0; c < 4; c++) s += pq_s[w][l + 32 * c];
#pragma unroll
        for (int off = 16; off; off >>= 1)
            s += __shfl_xor_sync(0xffffffffu, s, off);
        if (l == 0) inv_s[w] = 1.f / s;
    }
    __syncthreads();

    // ---- write s (normalized) ----
    {
        const int h0p = g * 4;
#pragma unroll
        for (int hh = 0; hh < 4; hh++) {
            float inv = inv_s[h0p + hh];
            float4 o;
            UNPACK2(o.x, o.y, accv[hh][0]);
            UNPACK2(o.z, o.w, accv[hh][1]);
            o.x *= inv; o.y *= inv; o.z *= inv; o.w *= inv;
            *(float4*)&g_s[(((size_t)(n * 8 + h0p + hh) * 128 + i)) * 512 + e0] = o;
        }
    }
    // ---- write normalized aw ----
#pragma unroll
    for (int u = 0; u < 4; u++) {
        int c = t + 256 * u;
        int h = c >> 7, j = c & 127;
        g_aw[(((size_t)(n * 8 + h) * 128 + i)) * 128 + j] = pq_s[h][j] * inv_s[h];
    }
}

// ---------------- K4b: attn GEMM, reg-double-buffered (1 bar/step) ----------
// (round-10 measured version: 43.1us, frozen)
__global__ __launch_bounds__(256) void k4b_attn(const float* __restrict__ Wknow) {
    __shared__ float As[2][32][128];
    __shared__ float Bs[2][32][64];
    const int n = blockIdx.x;
    const int h = blockIdx.y;
    const int t = threadIdx.x;
    const int ty = t >> 4, tx = t & 15;
    const int rr = t >> 1;            // A row
    const int kq = (t & 1) * 16;      // A col chunk

    const size_t bhrow = ((size_t)(n * 8 + h)) * 128;

    float4 pa[4], pb[2];
    auto gload = [&](int k0) {
        const float* p = (k0 < 128)
            ? &g_aw[(bhrow + rr) * 128 + k0 + kq]
            : &g_s[(bhrow + rr) * 512 + (k0 - 128) + kq];
        pa[0] = *(const float4*)p;
        pa[1] = *(const float4*)(p + 4);
        pa[2] = *(const float4*)(p + 8);
        pa[3] = *(const float4*)(p + 12);
        if (k0 < 128) {
            const int kr = t >> 3, dq = (t & 7) * 8;
            const float* q = &g_v[(bhrow + (k0 + kr)) * 64 + dq];
            pb[0] = *(const float4*)q;
            pb[1] = *(const float4*)(q + 4);
        } else {
            const int d = t >> 2, eq = (t & 3) * 8;
            const float* q = Wknow + (size_t)(h * 64 + d) * 512 + (k0 - 128) + eq;
            pb[0] = *(const float4*)q;
            pb[1] = *(const float4*)(q + 4);
        }
    };
    auto sstore = [&](int k0, int bf) {
#pragma unroll
        for (int c = 0; c < 4; c++) {
            As[bf][kq + 4 * c + 0][rr] = pa[c].x;
            As[bf][kq + 4 * c + 1][rr] = pa[c].y;
            As[bf][kq + 4 * c + 2][rr] = pa[c].z;
            As[bf][kq + 4 * c + 3][rr] = pa[c].w;
        }
        if (k0 < 128) {
            const int kr = t >> 3, dq = (t & 7) * 8;
            *(float4*)&Bs[bf][kr][dq]     = pb[0];
            *(float4*)&Bs[bf][kr][dq + 4] = pb[1];
        } else {
            const int d = t >> 2, eq = (t & 3) * 8;
            Bs[bf][eq + 0][d] = pb[0].x; Bs[bf][eq + 1][d] = pb[0].y;
            Bs[bf][eq + 2][d] = pb[0].z; Bs[bf][eq + 3][d] = pb[0].w;
            Bs[bf][eq + 4][d] = pb[1].x; Bs[bf][eq + 5][d] = pb[1].y;
            Bs[bf][eq + 6][d] = pb[1].z; Bs[bf][eq + 7][d] = pb[1].w;
        }
    };

    ull_t acc2[8][2];
#pragma unroll
    for (int a = 0; a < 8; a++) { acc2[a][0] = 0ull; acc2[a][1] = 0ull; }

    gload(0); sstore(0, 0); __syncthreads();
    int buf = 0;
#pragma unroll 1
    for (int k0 = 0; k0 < 640; k0 += 32) {
        if (k0 < 608) gload(k0 + 32);
#pragma unroll
        for (int kk = 0; kk < 32; kk++) {
            float a[8];
            *(float4*)(a)     = *(float4*)&As[buf][kk][ty * 8];
            *(float4*)(a + 4) = *(float4*)&As[buf][kk][ty * 8 + 4];
            ulonglong2 b2 = *(ulonglong2*)&Bs[buf][kk][tx * 4];
#pragma unroll
            for (int p = 0; p < 8; p++) {
                ull_t ap; PACK2(ap, a[p], a[p]);
                FMA2(acc2[p][0], ap, b2.x);
                FMA2(acc2[p][1], ap, b2.y);
            }
        }
        if (k0 < 608) sstore(k0 + 32, buf ^ 1);
        __syncthreads();
        buf ^= 1;
    }
#pragma unroll
    for (int ry = 0; ry < 8; ry++) {
        const int i = ty * 8 + ry;
        float4 o;
        UNPACK2(o.x, o.y, acc2[ry][0]);
        UNPACK2(o.z, o.w, acc2[ry][1]);
        float* dst = g_attn + ((size_t)i * 16 + n) * 512 + h * 64 + tx * 4;
        *(float4*)dst = o;
    }
}

// ---------------- K5: gating  out = g*r + (1-g)*attn ------------------------
__global__ __launch_bounds__(128) void k5_gate(const float* __restrict__ Wbeta,
                                               float* __restrict__ out) {
    const int m = blockIdx.x;
    const int t = threadIdx.x;
    const int w = t >> 5, l = t & 31;
    __shared__ float red[4];

    const float* a = g_attn + (size_t)m * 512;
    const float* r = g_r + (size_t)m * 512;

    float z = 0.f;
#pragma unroll
    for (int c = 0; c < 4; c++) {
        int e = t + 128 * c;
        float av = a[e], rv = r[e];
        z += Wbeta[e] * av + Wbeta[512 + e] * rv + Wbeta[1024 + e] * (av - rv);
    }
#pragma unroll
    for (int off = 16; off; off >>= 1)
        z += __shfl_xor_sync(0xffffffffu, z, off);
    if (l == 0) red[w] = z;
    __syncthreads();
    float zt = red[0] + red[1] + red[2] + red[3];
    float g = 1.f / (1.f + __expf(-zt));

#pragma unroll
    for (int c = 0; c < 4; c++) {
        int e = t + 128 * c;
        out[(size_t)m * 512 + e] = g * r[e] + (1.f - g) * a[e];
    }
}

// ---------------- launch -----------------------------------------------------
extern "C" void kernel_launch(void* const* d_in, const int* in_sizes, int n_in,
                              void* d_out, int out_size) {
    const float* x     = (const float*)d_in[0];
    const float* know  = (const float*)d_in[1];
    const int*   mask  = (const int*)d_in[2];
    const float* Wq    = (const float*)d_in[3];
    const float* Wk    = (const float*)d_in[4];
    const float* Wv    = (const float*)d_in[5];
    const float* Wknow = (const float*)d_in[6];
    const float* Wskip = (const float*)d_in[7];
    const float* Wbeta = (const float*)d_in[8];
    float* out = (float*)d_out;

    k1_proj<<<dim3(16, 16), 256>>>(x, Wq, Wk, Wv, Wskip);
    k23<<<640, 256>>>(Wknow);
    k34_onepass<<<2048, 256>>>(know, mask);
    k4b_attn<<<dim3(16, 8), 256>>>(Wknow);
    k5_gate<<<2048, 128>>>(Wbeta, out);
}

// round 14
// speedup vs baseline: 1.1387x; 1.0587x over previous
#include <cuda_runtime.h>
#include <cstdint>

#define SLEN 128
#define BSZ  16
#define EMB  512
#define NHEAD 8
#define HDIM 64
#define BH   (BSZ*NHEAD)   // 128
#define NEG_INF (-1e9f)
#define SCALING 0.125f     // 1/sqrt(64)

// ---- f32x2 packed math (Blackwell) ----
#define FMA2(d, a, b) asm("fma.rn.f32x2 %0, %1, %2, %0;" : "+l"(d) : "l"(a), "l"(b))
#define PACK2(u, lo, hi) asm("mov.b64 %0, {%1, %2};" : "=l"(u) : "f"(lo), "f"(hi))
#define UNPACK2(lo, hi, u) asm("mov.b64 {%0, %1}, %2;" : "=f"(lo), "=f"(hi) : "l"(u))

typedef unsigned long long ull_t;

__device__ __forceinline__ void cpa16(uint32_t saddr, const void* gaddr) {
    asm volatile("cp.async.ca.shared.global [%0], [%1], 16;" :: "r"(saddr), "l"(gaddr));
}
__device__ __forceinline__ void cpa_commit() {
    asm volatile("cp.async.commit_group;");
}
__device__ __forceinline__ void cpa_wait_all() {
    asm volatile("cp.async.wait_group 0;");
}

// ---------------- scratch (device globals; no runtime alloc) ----------------
__device__ float g_q[BH*SLEN*HDIM];        // [b][i][d]
__device__ float g_k[BH*SLEN*HDIM];        // [b][j][d]
__device__ float g_v[BH*SLEN*HDIM];        // [b][j][d]
__device__ float g_r[SLEN*BSZ*EMB];        // [m][e]
__device__ float g_qW[BH*SLEN*EMB];        // [b][i][e]
__device__ float g_aw[BH*SLEN*SLEN];       // [b][i][j]  (qk base, then normalized aw)
__device__ float g_s[BH*SLEN*EMB];         // [b][i][e]
__device__ float g_attn[SLEN*BSZ*EMB];     // [m][e]

// ---------------- K1: fused projections  C = X(2048x512) @ W^T --------------
// (round-9 measured version, reverted)
__global__ __launch_bounds__(256) void k1_proj(const float* __restrict__ x,
                                               const float* __restrict__ Wq,
                                               const float* __restrict__ Wk,
                                               const float* __restrict__ Wv,
                                               const float* __restrict__ Wskip) {
    __shared__ float As[16][128];
    __shared__ float Bs[16][128];
    const int m0 = blockIdx.y * 128;
    const int c0 = blockIdx.x * 128;
    const int sel = c0 >> 9;
    const float* W = (sel == 0) ? Wq : (sel == 1) ? Wk : (sel == 2) ? Wv : Wskip;
    const int e0 = c0 & 511;

    const int t  = threadIdx.x;
    const int ty = t >> 4, tx = t & 15;
    const int lr = t >> 1;
    const int lc = (t & 1) * 8;

    ull_t acc2[8][4];
#pragma unroll
    for (int a = 0; a < 8; a++)
#pragma unroll
        for (int b = 0; b < 4; b++) acc2[a][b] = 0ull;

    for (int k0 = 0; k0 < 512; k0 += 16) {
        float4 a0 = *(const float4*)(x + (size_t)(m0 + lr) * 512 + k0 + lc);
        float4 a1 = *(const float4*)(x + (size_t)(m0 + lr) * 512 + k0 + lc + 4);
        float4 b0 = *(const float4*)(W + (size_t)(e0 + lr) * 512 + k0 + lc);
        float4 b1 = *(const float4*)(W + (size_t)(e0 + lr) * 512 + k0 + lc + 4);
        As[lc + 0][lr] = a0.x; As[lc + 1][lr] = a0.y;
        As[lc + 2][lr] = a0.z; As[lc + 3][lr] = a0.w;
        As[lc + 4][lr] = a1.x; As[lc + 5][lr] = a1.y;
        As[lc + 6][lr] = a1.z; As[lc + 7][lr] = a1.w;
        Bs[lc + 0][lr] = b0.x; Bs[lc + 1][lr] = b0.y;
        Bs[lc + 2][lr] = b0.z; Bs[lc + 3][lr] = b0.w;
        Bs[lc + 4][lr] = b1.x; Bs[lc + 5][lr] = b1.y;
        Bs[lc + 6][lr] = b1.z; Bs[lc + 7][lr] = b1.w;
        __syncthreads();
#pragma unroll
        for (int kk = 0; kk < 16; kk++) {
            float a[8];
            *(float4*)(a)     = *(float4*)&As[kk][ty * 8];
            *(float4*)(a + 4) = *(float4*)&As[kk][ty * 8 + 4];
            ulonglong2 bA = *(ulonglong2*)&Bs[kk][tx * 8];
            ulonglong2 bB = *(ulonglong2*)&Bs[kk][tx * 8 + 4];
#pragma unroll
            for (int p = 0; p < 8; p++) {
                ull_t ap; PACK2(ap, a[p], a[p]);
                FMA2(acc2[p][0], ap, bA.x);
                FMA2(acc2[p][1], ap, bA.y);
                FMA2(acc2[p][2], ap, bB.x);
                FMA2(acc2[p][3], ap, bB.y);
            }
        }
        __syncthreads();
    }

    const int ecol = e0 + tx * 8;
    const int h = ecol >> 6;
    const int d0 = ecol & 63;
#pragma unroll
    for (int ry = 0; ry < 8; ry++) {
        const int m = m0 + ty * 8 + ry;
        const int i = m >> 4, n = m & 15;
        float o[8];
#pragma unroll
        for (int q = 0; q < 4; q++) UNPACK2(o[2*q], o[2*q+1], acc2[ry][q]);
        if (sel == 3) {
            float* dst = g_r + (size_t)m * 512 + ecol;
            *(float4*)dst       = *(float4*)&o[0];
            *(float4*)(dst + 4) = *(float4*)&o[4];
        } else {
            float* base = (sel == 0) ? g_q : (sel == 1) ? g_k : g_v;
            float* dst = base + ((size_t)(n * 8 + h) * 128 + i) * 64 + d0;
            *(float4*)dst       = *(float4*)&o[0];
            *(float4*)(dst + 4) = *(float4*)&o[4];
        }
    }
}

// ---------------- K23: merged qW GEMM (blocks 0..511) + q.k base (512..639) -
__global__ __launch_bounds__(256) void k23(const float* __restrict__ Wknow) {
    __shared__ float sm[8192];   // 32 KB, unioned
    const int t = threadIdx.x;
    const int bx = blockIdx.x;

    if (bx < 512) {
        float (*As)[128] = (float(*)[128])sm;
        float (*Bs)[128] = (float(*)[128])(sm + 16 * 128);
        const int h = bx >> 6;
        const int sub = bx & 63;
        const int m0 = (sub & 15) * 128;
        const int e0t = (sub >> 4) * 128;

        const int ty = t >> 4, tx = t & 15;
        const int lr = t >> 1;
        const int lc = (t & 1) * 8;
        const int dr = t >> 4;
        const int ec = (t & 15) * 8;

        ull_t acc2[8][4];
#pragma unroll
        for (int a = 0; a < 8; a++)
#pragma unroll
            for (int b = 0; b < 4; b++) acc2[a][b] = 0ull;

        for (int k0 = 0; k0 < 64; k0 += 16) {
            {
                const int m = m0 + lr;
                const int n = m >> 7, i = m & 127;
                const float* ar = &g_q[((size_t)(n * 8 + h) * 128 + i) * 64 + k0 + lc];
                float4 a0 = *(const float4*)ar;
                float4 a1 = *(const float4*)(ar + 4);
                As[lc + 0][lr] = a0.x; As[lc + 1][lr] = a0.y;
                As[lc + 2][lr] = a0.z; As[lc + 3][lr] = a0.w;
                As[lc + 4][lr] = a1.x; As[lc + 5][lr] = a1.y;
                As[lc + 6][lr] = a1.z; As[lc + 7][lr] = a1.w;
            }
            {
                const float* br = Wknow + (size_t)(h * 64 + k0 + dr) * 512 + e0t + ec;
                float4 b0 = *(const float4*)br;
                float4 b1 = *(const float4*)(br + 4);
                *(float4*)&Bs[dr][ec]     = b0;
                *(float4*)&Bs[dr][ec + 4] = b1;
            }
            __syncthreads();
#pragma unroll
            for (int kk = 0; kk < 16; kk++) {
                float a[8];
                *(float4*)(a)     = *(float4*)&As[kk][ty * 8];
                *(float4*)(a + 4) = *(float4*)&As[kk][ty * 8 + 4];
                ulonglong2 bA = *(ulonglong2*)&Bs[kk][tx * 8];
                ulonglong2 bB = *(ulonglong2*)&Bs[kk][tx * 8 + 4];
#pragma unroll
                for (int p = 0; p < 8; p++) {
                    ull_t ap; PACK2(ap, a[p], a[p]);
                    FMA2(acc2[p][0], ap, bA.x);
                    FMA2(acc2[p][1], ap, bA.y);
                    FMA2(acc2[p][2], ap, bB.x);
                    FMA2(acc2[p][3], ap, bB.y);
                }
            }
            __syncthreads();
        }
#pragma unroll
        for (int ry = 0; ry < 8; ry++) {
            const int m = m0 + ty * 8 + ry;
            const int n = m >> 7, i = m & 127;
            float o[8];
#pragma unroll
            for (int q = 0; q < 4; q++) UNPACK2(o[2*q], o[2*q+1], acc2[ry][q]);
            float* dst = &g_qW[((size_t)(n * 8 + h) * 128 + i) * 512 + e0t + tx * 8];
            *(float4*)dst       = *(float4*)&o[0];
            *(float4*)(dst + 4) = *(float4*)&o[4];
        }
    } else {
        float (*qT)[128] = (float(*)[128])sm;
        float (*kT)[128] = (float(*)[128])(sm + 32 * 128);
        const int b = bx - 512;
        const int ty = t >> 4, tx = t & 15;

        float acc[8][8];
#pragma unroll
        for (int p = 0; p < 8; p++)
#pragma unroll
            for (int q = 0; q < 8; q++) acc[p][q] = 0.f;

        for (int d0 = 0; d0 < 64; d0 += 32) {
#pragma unroll
            for (int u = 0; u < 4; u++) {
                int ii = (t >> 3) + 32 * u;
                int d4 = (t & 7) * 4;
                float4 a = *(const float4*)&g_q[((size_t)b * 128 + ii) * 64 + d0 + d4];
                qT[d4 + 0][ii] = a.x; qT[d4 + 1][ii] = a.y;
                qT[d4 + 2][ii] = a.z; qT[d4 + 3][ii] = a.w;
                float4 bb = *(const float4*)&g_k[((size_t)b * 128 + ii) * 64 + d0 + d4];
                kT[d4 + 0][ii] = bb.x; kT[d4 + 1][ii] = bb.y;
                kT[d4 + 2][ii] = bb.z; kT[d4 + 3][ii] = bb.w;
            }
            __syncthreads();
#pragma unroll
            for (int d = 0; d < 32; d++) {
                float a[8], bl[8];
                *(float4*)(a)      = *(float4*)&qT[d][ty * 8];
                *(float4*)(a + 4)  = *(float4*)&qT[d][ty * 8 + 4];
                *(float4*)(bl)     = *(float4*)&kT[d][tx * 8];
                *(float4*)(bl + 4) = *(float4*)&kT[d][tx * 8 + 4];
#pragma unroll
                for (int p = 0; p < 8; p++)
#pragma unroll
                    for (int q = 0; q < 8; q++) acc[p][q] += a[p] * bl[q];
            }
            __syncthreads();
        }
#pragma unroll
        for (int p = 0; p < 8; p++) {
            float* dst = &g_aw[((size_t)b * 128 + ty * 8 + p) * 128 + tx * 8];
            *(float4*)dst       = *(float4*)&acc[p][0];
            *(float4*)(dst + 4) = *(float4*)&acc[p][4];
        }
    }
}

// ---------------- K34: ONE-PASS logits + exp + s-accum over know ------------
// (round-7/11 version: best measured, FROZEN)
#define TJ 16
__global__ __launch_bounds__(256, 2) void k34_onepass(const float* __restrict__ know,
                                                      const int* __restrict__ mask) {
    __shared__ float kn_s[2][TJ][512];   // 64 KB (double buffer)
    __shared__ ull_t pT2[TJ][8];         // 1 KB  (packed (p,p))
    __shared__ float pq_s[8][128];       // 4 KB  (qk base -> unnormalized p)
    __shared__ unsigned char m8[8][128]; // 1 KB
    __shared__ float inv_s[8];

    const int n = blockIdx.x >> 7;
    const int i = blockIdx.x & 127;
    const int t = threadIdx.x, w = t >> 5, l = t & 31;
    const int hg = w & 1, jq = w >> 1;           // phase-1 warp role
    const int h0 = hg * 4;
    const int g = t >> 7;                        // phase-3 h-group (0/1)
    const int e0 = (t & 127) << 2;               // phase-3 e-chunk

    // ---- preload q.k base (into pq_s) + mask ----
    {
        int h = t >> 5, j0 = (t & 31) << 2;
        *(float4*)&pq_s[h][j0] =
            *(const float4*)&g_aw[(((size_t)(n * 8 + h) * 128 + i)) * 128 + j0];
        int4 mm = *(const int4*)&mask[(((size_t)(n * 8 + h) * 128 + i)) * 128 + j0];
        uchar4 mb;
        mb.x = (unsigned char)(mm.x != 0); mb.y = (unsigned char)(mm.y != 0);
        mb.z = (unsigned char)(mm.z != 0); mb.w = (unsigned char)(mm.w != 0);
        *(uchar4*)&m8[h][j0] = mb;
    }

    // ---- qW slices into registers: 4 heads x full 512e, e = 4l + 128u ----
    ulonglong2 qw[4][4];
#pragma unroll
    for (int h = 0; h < 4; h++) {
        const float* qb = &g_qW[(((size_t)(n * 8 + h0 + h) * 128 + i)) * 512 + 4 * l];
#pragma unroll
        for (int u = 0; u < 4; u++)
            qw[h][u] = *(const ulonglong2*)(qb + 128 * u);
    }

    const float* knbase = know + ((size_t)n * 16384 + (size_t)i * 128) * 512;
    const uint32_t kn_sa = (uint32_t)__cvta_generic_to_shared(&kn_s[0][0][0]);

    ull_t accv[4][2];
#pragma unroll
    for (int hh = 0; hh < 4; hh++) { accv[hh][0] = 0ull; accv[hh][1] = 0ull; }

    // ---- prologue: stage tile 0 into buf 0 via cp.async ----
#pragma unroll
    for (int u = 0; u < 8; u++) {
        int c = t + 256 * u;
        int r = c >> 7, ch = c & 127;
        cpa16(kn_sa + (uint32_t)(r * 2048 + ch * 16),
              knbase + (size_t)r * 512 + ch * 4);
    }
    cpa_commit();

    int buf = 0;
#pragma unroll 1
    for (int tt = 0; tt < 8; tt++) {
        cpa_wait_all();
        __syncthreads();   // tile[buf] visible; prev phase3 done with pT2

        if (tt < 7) {
            const float* nb = knbase + (size_t)(tt + 1) * TJ * 512;
            const uint32_t sb = kn_sa + (uint32_t)((buf ^ 1) * TJ * 2048);
#pragma unroll
            for (int u = 0; u < 8; u++) {
                int c = t + 256 * u;
                int r = c >> 7, ch = c & 127;
                cpa16(sb + (uint32_t)(r * 2048 + ch * 16),
                      nb + (size_t)r * 512 + ch * 4);
            }
            cpa_commit();
        }

        // ---- phase 1: full logits, inline exp; warp does 4 j rows ----
#pragma unroll
        for (int jj = 0; jj < 4; jj++) {
            const int jl = jq * 4 + jj;
            const int j = tt * TJ + jl;
            ulonglong2 kv[4];
#pragma unroll
            for (int u = 0; u < 4; u++)
                kv[u] = *(const ulonglong2*)&kn_s[buf][jl][4 * l + 128 * u];
            ull_t a2[4];
#pragma unroll
            for (int h = 0; h < 4; h++) a2[h] = 0ull;
#pragma unroll
            for (int h = 0; h < 4; h++)
#pragma unroll
                for (int u = 0; u < 4; u++) {
                    FMA2(a2[h], kv[u].x, qw[h][u].x);
                    FMA2(a2[h], kv[u].y, qw[h][u].y);
                }
            float v[4];
#pragma unroll
            for (int h = 0; h < 4; h++) {
                float lo, hi; UNPACK2(lo, hi, a2[h]); v[h] = lo + hi;
            }
#pragma unroll
            for (int h = 0; h < 2; h++) {
                float give = (l & 16) ? v[h] : v[h + 2];
                float keep = (l & 16) ? v[h + 2] : v[h];
                v[h] = keep + __shfl_xor_sync(0xffffffffu, give, 16);
            }
            {
                float give = (l & 8) ? v[0] : v[1];
                float keep = (l & 8) ? v[1] : v[0];
                v[0] = keep + __shfl_xor_sync(0xffffffffu, give, 8);
            }
            v[0] += __shfl_xor_sync(0xffffffffu, v[0], 4);
            v[0] += __shfl_xor_sync(0xffffffffu, v[0], 2);
            v[0] += __shfl_xor_sync(0xffffffffu, v[0], 1);
            if ((l & 7) == 0) {
                const int h = h0 + ((l >> 4) & 1) * 2 + ((l >> 3) & 1);
                float lg = (v[0] + pq_s[h][j]) * SCALING;
                float p = m8[h][j] ? __expf(lg) : 0.f;
                pq_s[h][j] = p;
                ull_t p2; PACK2(p2, p, p);
                pT2[jl][h] = p2;
            }
        }
        __syncthreads();   // p ready

        // ---- phase 3: s accumulation from same tile ----
        {
            const int h0p = g * 4;
#pragma unroll
            for (int jl = 0; jl < TJ; jl++) {
                ulonglong2 kv = *(const ulonglong2*)&kn_s[buf][jl][e0];
                ulonglong2 pa = *(const ulonglong2*)&pT2[jl][h0p];
                ulonglong2 pb = *(const ulonglong2*)&pT2[jl][h0p + 2];
                FMA2(accv[0][0], pa.x, kv.x); FMA2(accv[0][1], pa.x, kv.y);
                FMA2(accv[1][0], pa.y, kv.x); FMA2(accv[1][1], pa.y, kv.y);
                FMA2(accv[2][0], pb.x, kv.x); FMA2(accv[2][1], pb.x, kv.y);
                FMA2(accv[3][0], pb.y, kv.x); FMA2(accv[3][1], pb.y, kv.y);
            }
        }
        buf ^= 1;
    }

    // ---- normalization: warp w sums p over head w ----
    {
        float s = 0.f;
#pragma unroll
        for (int c = 0; c < 4; c++) s += pq_s[w][l + 32 * c];
#pragma unroll
        for (int off = 16; off; off >>= 1)
            s += __shfl_xor_sync(0xffffffffu, s, off);
        if (l == 0) inv_s[w] = 1.f / s;
    }
    __syncthreads();

    // ---- write s (normalized) ----
    {
        const int h0p = g * 4;
#pragma unroll
        for (int hh = 0; hh < 4; hh++) {
            float inv = inv_s[h0p + hh];
            float4 o;
            UNPACK2(o.x, o.y, accv[hh][0]);
            UNPACK2(o.z, o.w, accv[hh][1]);
            o.x *= inv; o.y *= inv; o.z *= inv; o.w *= inv;
            *(float4*)&g_s[(((size_t)(n * 8 + h0p + hh) * 128 + i)) * 512 + e0] = o;
        }
    }
    // ---- write normalized aw ----
#pragma unroll
    for (int u = 0; u < 4; u++) {
        int c = t + 256 * u;
        int h = c >> 7, j = c & 127;
        g_aw[(((size_t)(n * 8 + h) * 128 + i)) * 128 + j] = pq_s[h][j] * inv_s[h];
    }
}

// ---------------- K4b: attn GEMM, BM=64 + double buffer (grid 256 blocks) ---
// BM=64, BN=64, BK=32; grid (32, 8); thread = 4 rows x 4 cols.
__global__ __launch_bounds__(256) void k4b_attn(const float* __restrict__ Wknow) {
    __shared__ float As[2][32][64];
    __shared__ float Bs[2][32][64];
    const int n = blockIdx.x >> 1;
    const int i0 = (blockIdx.x & 1) * 64;
    const int h = blockIdx.y;
    const int t = threadIdx.x;
    const int ty = t >> 4, tx = t & 15;
    const int rr = t >> 2;            // A row (0..63)
    const int kq = (t & 3) * 8;       // A col chunk (8 floats)

    const size_t bhrow = ((size_t)(n * 8 + h)) * 128;

    float4 pa[2], pb[2];
    auto gload = [&](int k0) {
        const float* p = (k0 < 128)
            ? &g_aw[(bhrow + i0 + rr) * 128 + k0 + kq]
            : &g_s[(bhrow + i0 + rr) * 512 + (k0 - 128) + kq];
        pa[0] = *(const float4*)p;
        pa[1] = *(const float4*)(p + 4);
        if (k0 < 128) {
            const int kr = t >> 3, dq = (t & 7) * 8;
            const float* q = &g_v[(bhrow + (k0 + kr)) * 64 + dq];
            pb[0] = *(const float4*)q;
            pb[1] = *(const float4*)(q + 4);
        } else {
            const int d = t >> 2, eq = (t & 3) * 8;
            const float* q = Wknow + (size_t)(h * 64 + d) * 512 + (k0 - 128) + eq;
            pb[0] = *(const float4*)q;
            pb[1] = *(const float4*)(q + 4);
        }
    };
    auto sstore = [&](int k0, int bf) {
#pragma unroll
        for (int c = 0; c < 2; c++) {
            As[bf][kq + 4 * c + 0][rr] = pa[c].x;
            As[bf][kq + 4 * c + 1][rr] = pa[c].y;
            As[bf][kq + 4 * c + 2][rr] = pa[c].z;
            As[bf][kq + 4 * c + 3][rr] = pa[c].w;
        }
        if (k0 < 128) {
            const int kr = t >> 3, dq = (t & 7) * 8;
            *(float4*)&Bs[bf][kr][dq]     = pb[0];
            *(float4*)&Bs[bf][kr][dq + 4] = pb[1];
        } else {
            const int d = t >> 2, eq = (t & 3) * 8;
            Bs[bf][eq + 0][d] = pb[0].x; Bs[bf][eq + 1][d] = pb[0].y;
            Bs[bf][eq + 2][d] = pb[0].z; Bs[bf][eq + 3][d] = pb[0].w;
            Bs[bf][eq + 4][d] = pb[1].x; Bs[bf][eq + 5][d] = pb[1].y;
            Bs[bf][eq + 6][d] = pb[1].z; Bs[bf][eq + 7][d] = pb[1].w;
        }
    };

    ull_t acc2[4][2];
#pragma unroll
    for (int a = 0; a < 4; a++) { acc2[a][0] = 0ull; acc2[a][1] = 0ull; }

    gload(0); sstore(0, 0); __syncthreads();
    int buf = 0;
#pragma unroll 1
    for (int k0 = 0; k0 < 640; k0 += 32) {
        if (k0 < 608) gload(k0 + 32);
#pragma unroll
        for (int kk = 0; kk < 32; kk++) {
            float4 a4 = *(float4*)&As[buf][kk][ty * 4];
            ulonglong2 b2 = *(ulonglong2*)&Bs[buf][kk][tx * 4];
            ull_t ap;
            PACK2(ap, a4.x, a4.x); FMA2(acc2[0][0], ap, b2.x); FMA2(acc2[0][1], ap, b2.y);
            PACK2(ap, a4.y, a4.y); FMA2(acc2[1][0], ap, b2.x); FMA2(acc2[1][1], ap, b2.y);
            PACK2(ap, a4.z, a4.z); FMA2(acc2[2][0], ap, b2.x); FMA2(acc2[2][1], ap, b2.y);
            PACK2(ap, a4.w, a4.w); FMA2(acc2[3][0], ap, b2.x); FMA2(acc2[3][1], ap, b2.y);
        }
        if (k0 < 608) sstore(k0 + 32, buf ^ 1);
        __syncthreads();
        buf ^= 1;
    }
#pragma unroll
    for (int ry = 0; ry < 4; ry++) {
        const int i = i0 + ty * 4 + ry;
        float4 o;
        UNPACK2(o.x, o.y, acc2[ry][0]);
        UNPACK2(o.z, o.w, acc2[ry][1]);
        float* dst = g_attn + ((size_t)i * 16 + n) * 512 + h * 64 + tx * 4;
        *(float4*)dst = o;
    }
}

// ---------------- K5: gating  out = g*r + (1-g)*attn ------------------------
__global__ __launch_bounds__(128) void k5_gate(const float* __restrict__ Wbeta,
                                               float* __restrict__ out) {
    const int m = blockIdx.x;
    const int t = threadIdx.x;
    const int w = t >> 5, l = t & 31;
    __shared__ float red[4];

    const float* a = g_attn + (size_t)m * 512;
    const float* r = g_r + (size_t)m * 512;

    float z = 0.f;
#pragma unroll
    for (int c = 0; c < 4; c++) {
        int e = t + 128 * c;
        float av = a[e], rv = r[e];
        z += Wbeta[e] * av + Wbeta[512 + e] * rv + Wbeta[1024 + e] * (av - rv);
    }
#pragma unroll
    for (int off = 16; off; off >>= 1)
        z += __shfl_xor_sync(0xffffffffu, z, off);
    if (l == 0) red[w] = z;
    __syncthreads();
    float zt = red[0] + red[1] + red[2] + red[3];
    float g = 1.f / (1.f + __expf(-zt));

#pragma unroll
    for (int c = 0; c < 4; c++) {
        int e = t + 128 * c;
        out[(size_t)m * 512 + e] = g * r[e] + (1.f - g) * a[e];
    }
}

// ---------------- launch -----------------------------------------------------
extern "C" void kernel_launch(void* const* d_in, const int* in_sizes, int n_in,
                              void* d_out, int out_size) {
    const float* x     = (const float*)d_in[0];
    const float* know  = (const float*)d_in[1];
    const int*   mask  = (const int*)d_in[2];
    const float* Wq    = (const float*)d_in[3];
    const float* Wk    = (const float*)d_in[4];
    const float* Wv    = (const float*)d_in[5];
    const float* Wknow = (const float*)d_in[6];
    const float* Wskip = (const float*)d_in[7];
    const float* Wbeta = (const float*)d_in[8];
    float* out = (float*)d_out;

    k1_proj<<<dim3(16, 16), 256>>>(x, Wq, Wk, Wv, Wskip);
    k23<<<640, 256>>>(Wknow);
    k34_onepass<<<2048, 256>>>(know, mask);
    k4b_attn<<<dim3(32, 8), 256>>>(Wknow);
    k5_gate<<<2048, 128>>>(Wbeta, out);
}

// round 15
// speedup vs baseline: 1.1689x; 1.0265x over previous
#include <cuda_runtime.h>
#include <cstdint>

#define SLEN 128
#define BSZ  16
#define EMB  512
#define NHEAD 8
#define HDIM 64
#define BH   (BSZ*NHEAD)   // 128
#define NEG_INF (-1e9f)
#define SCALING 0.125f     // 1/sqrt(64)

// ---- f32x2 packed math (Blackwell) ----
#define FMA2(d, a, b) asm("fma.rn.f32x2 %0, %1, %2, %0;" : "+l"(d) : "l"(a), "l"(b))
#define PACK2(u, lo, hi) asm("mov.b64 %0, {%1, %2};" : "=l"(u) : "f"(lo), "f"(hi))
#define UNPACK2(lo, hi, u) asm("mov.b64 {%0, %1}, %2;" : "=f"(lo), "=f"(hi) : "l"(u))

typedef unsigned long long ull_t;

__device__ __forceinline__ void cpa16(uint32_t saddr, const void* gaddr) {
    asm volatile("cp.async.ca.shared.global [%0], [%1], 16;" :: "r"(saddr), "l"(gaddr));
}
__device__ __forceinline__ void cpa_commit() {
    asm volatile("cp.async.commit_group;");
}
__device__ __forceinline__ void cpa_wait_all() {
    asm volatile("cp.async.wait_group 0;");
}

// ---------------- scratch (device globals; no runtime alloc) ----------------
__device__ float g_q[BH*SLEN*HDIM];        // [b][i][d]
__device__ float g_k[BH*SLEN*HDIM];        // [b][j][d]
__device__ float g_v[BH*SLEN*HDIM];        // [b][j][d]
__device__ float g_r[SLEN*BSZ*EMB];        // [m][e]
__device__ float g_qW[BH*SLEN*EMB];        // [b][i][e]
__device__ float g_aw[BH*SLEN*SLEN];       // [b][i][j]  (qk base, then normalized aw)
__device__ float g_s[BH*SLEN*EMB];         // [b][i][e]
__device__ float g_attnA[SLEN*BSZ*EMB];    // [m][e] K-half 0 partial
__device__ float g_attnB[SLEN*BSZ*EMB];    // [m][e] K-half 1 partial

// ---------------- K1: fused projections  C = X(2048x512) @ W^T --------------
// (round-9 measured version)
__global__ __launch_bounds__(256) void k1_proj(const float* __restrict__ x,
                                               const float* __restrict__ Wq,
                                               const float* __restrict__ Wk,
                                               const float* __restrict__ Wv,
                                               const float* __restrict__ Wskip) {
    __shared__ float As[16][128];
    __shared__ float Bs[16][128];
    const int m0 = blockIdx.y * 128;
    const int c0 = blockIdx.x * 128;
    const int sel = c0 >> 9;
    const float* W = (sel == 0) ? Wq : (sel == 1) ? Wk : (sel == 2) ? Wv : Wskip;
    const int e0 = c0 & 511;

    const int t  = threadIdx.x;
    const int ty = t >> 4, tx = t & 15;
    const int lr = t >> 1;
    const int lc = (t & 1) * 8;

    ull_t acc2[8][4];
#pragma unroll
    for (int a = 0; a < 8; a++)
#pragma unroll
        for (int b = 0; b < 4; b++) acc2[a][b] = 0ull;

    for (int k0 = 0; k0 < 512; k0 += 16) {
        float4 a0 = *(const float4*)(x + (size_t)(m0 + lr) * 512 + k0 + lc);
        float4 a1 = *(const float4*)(x + (size_t)(m0 + lr) * 512 + k0 + lc + 4);
        float4 b0 = *(const float4*)(W + (size_t)(e0 + lr) * 512 + k0 + lc);
        float4 b1 = *(const float4*)(W + (size_t)(e0 + lr) * 512 + k0 + lc + 4);
        As[lc + 0][lr] = a0.x; As[lc + 1][lr] = a0.y;
        As[lc + 2][lr] = a0.z; As[lc + 3][lr] = a0.w;
        As[lc + 4][lr] = a1.x; As[lc + 5][lr] = a1.y;
        As[lc + 6][lr] = a1.z; As[lc + 7][lr] = a1.w;
        Bs[lc + 0][lr] = b0.x; Bs[lc + 1][lr] = b0.y;
        Bs[lc + 2][lr] = b0.z; Bs[lc + 3][lr] = b0.w;
        Bs[lc + 4][lr] = b1.x; Bs[lc + 5][lr] = b1.y;
        Bs[lc + 6][lr] = b1.z; Bs[lc + 7][lr] = b1.w;
        __syncthreads();
#pragma unroll
        for (int kk = 0; kk < 16; kk++) {
            float a[8];
            *(float4*)(a)     = *(float4*)&As[kk][ty * 8];
            *(float4*)(a + 4) = *(float4*)&As[kk][ty * 8 + 4];
            ulonglong2 bA = *(ulonglong2*)&Bs[kk][tx * 8];
            ulonglong2 bB = *(ulonglong2*)&Bs[kk][tx * 8 + 4];
#pragma unroll
            for (int p = 0; p < 8; p++) {
                ull_t ap; PACK2(ap, a[p], a[p]);
                FMA2(acc2[p][0], ap, bA.x);
                FMA2(acc2[p][1], ap, bA.y);
                FMA2(acc2[p][2], ap, bB.x);
                FMA2(acc2[p][3], ap, bB.y);
            }
        }
        __syncthreads();
    }

    const int ecol = e0 + tx * 8;
    const int h = ecol >> 6;
    const int d0 = ecol & 63;
#pragma unroll
    for (int ry = 0; ry < 8; ry++) {
        const int m = m0 + ty * 8 + ry;
        const int i = m >> 4, n = m & 15;
        float o[8];
#pragma unroll
        for (int q = 0; q < 4; q++) UNPACK2(o[2*q], o[2*q+1], acc2[ry][q]);
        if (sel == 3) {
            float* dst = g_r + (size_t)m * 512 + ecol;
            *(float4*)dst       = *(float4*)&o[0];
            *(float4*)(dst + 4) = *(float4*)&o[4];
        } else {
            float* base = (sel == 0) ? g_q : (sel == 1) ? g_k : g_v;
            float* dst = base + ((size_t)(n * 8 + h) * 128 + i) * 64 + d0;
            *(float4*)dst       = *(float4*)&o[0];
            *(float4*)(dst + 4) = *(float4*)&o[4];
        }
    }
}

// ---------------- K23: merged qW GEMM (blocks 0..511) + q.k base (512..639) -
__global__ __launch_bounds__(256) void k23(const float* __restrict__ Wknow) {
    __shared__ float sm[8192];   // 32 KB, unioned
    const int t = threadIdx.x;
    const int bx = blockIdx.x;

    if (bx < 512) {
        float (*As)[128] = (float(*)[128])sm;
        float (*Bs)[128] = (float(*)[128])(sm + 16 * 128);
        const int h = bx >> 6;
        const int sub = bx & 63;
        const int m0 = (sub & 15) * 128;
        const int e0t = (sub >> 4) * 128;

        const int ty = t >> 4, tx = t & 15;
        const int lr = t >> 1;
        const int lc = (t & 1) * 8;
        const int dr = t >> 4;
        const int ec = (t & 15) * 8;

        ull_t acc2[8][4];
#pragma unroll
        for (int a = 0; a < 8; a++)
#pragma unroll
            for (int b = 0; b < 4; b++) acc2[a][b] = 0ull;

        for (int k0 = 0; k0 < 64; k0 += 16) {
            {
                const int m = m0 + lr;
                const int n = m >> 7, i = m & 127;
                const float* ar = &g_q[((size_t)(n * 8 + h) * 128 + i) * 64 + k0 + lc];
                float4 a0 = *(const float4*)ar;
                float4 a1 = *(const float4*)(ar + 4);
                As[lc + 0][lr] = a0.x; As[lc + 1][lr] = a0.y;
                As[lc + 2][lr] = a0.z; As[lc + 3][lr] = a0.w;
                As[lc + 4][lr] = a1.x; As[lc + 5][lr] = a1.y;
                As[lc + 6][lr] = a1.z; As[lc + 7][lr] = a1.w;
            }
            {
                const float* br = Wknow + (size_t)(h * 64 + k0 + dr) * 512 + e0t + ec;
                float4 b0 = *(const float4*)br;
                float4 b1 = *(const float4*)(br + 4);
                *(float4*)&Bs[dr][ec]     = b0;
                *(float4*)&Bs[dr][ec + 4] = b1;
            }
            __syncthreads();
#pragma unroll
            for (int kk = 0; kk < 16; kk++) {
                float a[8];
                *(float4*)(a)     = *(float4*)&As[kk][ty * 8];
                *(float4*)(a + 4) = *(float4*)&As[kk][ty * 8 + 4];
                ulonglong2 bA = *(ulonglong2*)&Bs[kk][tx * 8];
                ulonglong2 bB = *(ulonglong2*)&Bs[kk][tx * 8 + 4];
#pragma unroll
                for (int p = 0; p < 8; p++) {
                    ull_t ap; PACK2(ap, a[p], a[p]);
                    FMA2(acc2[p][0], ap, bA.x);
                    FMA2(acc2[p][1], ap, bA.y);
                    FMA2(acc2[p][2], ap, bB.x);
                    FMA2(acc2[p][3], ap, bB.y);
                }
            }
            __syncthreads();
        }
#pragma unroll
        for (int ry = 0; ry < 8; ry++) {
            const int m = m0 + ty * 8 + ry;
            const int n = m >> 7, i = m & 127;
            float o[8];
#pragma unroll
            for (int q = 0; q < 4; q++) UNPACK2(o[2*q], o[2*q+1], acc2[ry][q]);
            float* dst = &g_qW[((size_t)(n * 8 + h) * 128 + i) * 512 + e0t + tx * 8];
            *(float4*)dst       = *(float4*)&o[0];
            *(float4*)(dst + 4) = *(float4*)&o[4];
        }
    } else {
        float (*qT)[128] = (float(*)[128])sm;
        float (*kT)[128] = (float(*)[128])(sm + 32 * 128);
        const int b = bx - 512;
        const int ty = t >> 4, tx = t & 15;

        float acc[8][8];
#pragma unroll
        for (int p = 0; p < 8; p++)
#pragma unroll
            for (int q = 0; q < 8; q++) acc[p][q] = 0.f;

        for (int d0 = 0; d0 < 64; d0 += 32) {
#pragma unroll
            for (int u = 0; u < 4; u++) {
                int ii = (t >> 3) + 32 * u;
                int d4 = (t & 7) * 4;
                float4 a = *(const float4*)&g_q[((size_t)b * 128 + ii) * 64 + d0 + d4];
                qT[d4 + 0][ii] = a.x; qT[d4 + 1][ii] = a.y;
                qT[d4 + 2][ii] = a.z; qT[d4 + 3][ii] = a.w;
                float4 bb = *(const float4*)&g_k[((size_t)b * 128 + ii) * 64 + d0 + d4];
                kT[d4 + 0][ii] = bb.x; kT[d4 + 1][ii] = bb.y;
                kT[d4 + 2][ii] = bb.z; kT[d4 + 3][ii] = bb.w;
            }
            __syncthreads();
#pragma unroll
            for (int d = 0; d < 32; d++) {
                float a[8], bl[8];
                *(float4*)(a)      = *(float4*)&qT[d][ty * 8];
                *(float4*)(a + 4)  = *(float4*)&qT[d][ty * 8 + 4];
                *(float4*)(bl)     = *(float4*)&kT[d][tx * 8];
                *(float4*)(bl + 4) = *(float4*)&kT[d][tx * 8 + 4];
#pragma unroll
                for (int p = 0; p < 8; p++)
#pragma unroll
                    for (int q = 0; q < 8; q++) acc[p][q] += a[p] * bl[q];
            }
            __syncthreads();
        }
#pragma unroll
        for (int p = 0; p < 8; p++) {
            float* dst = &g_aw[((size_t)b * 128 + ty * 8 + p) * 128 + tx * 8];
            *(float4*)dst       = *(float4*)&acc[p][0];
            *(float4*)(dst + 4) = *(float4*)&acc[p][4];
        }
    }
}

// ---------------- K34: ONE-PASS logits + exp + s-accum over know ------------
// (round-7/11 version: best measured, FROZEN)
#define TJ 16
__global__ __launch_bounds__(256, 2) void k34_onepass(const float* __restrict__ know,
                                                      const int* __restrict__ mask) {
    __shared__ float kn_s[2][TJ][512];   // 64 KB (double buffer)
    __shared__ ull_t pT2[TJ][8];         // 1 KB  (packed (p,p))
    __shared__ float pq_s[8][128];       // 4 KB  (qk base -> unnormalized p)
    __shared__ unsigned char m8[8][128]; // 1 KB
    __shared__ float inv_s[8];

    const int n = blockIdx.x >> 7;
    const int i = blockIdx.x & 127;
    const int t = threadIdx.x, w = t >> 5, l = t & 31;
    const int hg = w & 1, jq = w >> 1;           // phase-1 warp role
    const int h0 = hg * 4;
    const int g = t >> 7;                        // phase-3 h-group (0/1)
    const int e0 = (t & 127) << 2;               // phase-3 e-chunk

    // ---- preload q.k base (into pq_s) + mask ----
    {
        int h = t >> 5, j0 = (t & 31) << 2;
        *(float4*)&pq_s[h][j0] =
            *(const float4*)&g_aw[(((size_t)(n * 8 + h) * 128 + i)) * 128 + j0];
        int4 mm = *(const int4*)&mask[(((size_t)(n * 8 + h) * 128 + i)) * 128 + j0];
        uchar4 mb;
        mb.x = (unsigned char)(mm.x != 0); mb.y = (unsigned char)(mm.y != 0);
        mb.z = (unsigned char)(mm.z != 0); mb.w = (unsigned char)(mm.w != 0);
        *(uchar4*)&m8[h][j0] = mb;
    }

    // ---- qW slices into registers: 4 heads x full 512e, e = 4l + 128u ----
    ulonglong2 qw[4][4];
#pragma unroll
    for (int h = 0; h < 4; h++) {
        const float* qb = &g_qW[(((size_t)(n * 8 + h0 + h) * 128 + i)) * 512 + 4 * l];
#pragma unroll
        for (int u = 0; u < 4; u++)
            qw[h][u] = *(const ulonglong2*)(qb + 128 * u);
    }

    const float* knbase = know + ((size_t)n * 16384 + (size_t)i * 128) * 512;
    const uint32_t kn_sa = (uint32_t)__cvta_generic_to_shared(&kn_s[0][0][0]);

    ull_t accv[4][2];
#pragma unroll
    for (int hh = 0; hh < 4; hh++) { accv[hh][0] = 0ull; accv[hh][1] = 0ull; }

    // ---- prologue: stage tile 0 into buf 0 via cp.async ----
#pragma unroll
    for (int u = 0; u < 8; u++) {
        int c = t + 256 * u;
        int r = c >> 7, ch = c & 127;
        cpa16(kn_sa + (uint32_t)(r * 2048 + ch * 16),
              knbase + (size_t)r * 512 + ch * 4);
    }
    cpa_commit();

    int buf = 0;
#pragma unroll 1
    for (int tt = 0; tt < 8; tt++) {
        cpa_wait_all();
        __syncthreads();   // tile[buf] visible; prev phase3 done with pT2

        if (tt < 7) {
            const float* nb = knbase + (size_t)(tt + 1) * TJ * 512;
            const uint32_t sb = kn_sa + (uint32_t)((buf ^ 1) * TJ * 2048);
#pragma unroll
            for (int u = 0; u < 8; u++) {
                int c = t + 256 * u;
                int r = c >> 7, ch = c & 127;
                cpa16(sb + (uint32_t)(r * 2048 + ch * 16),
                      nb + (size_t)r * 512 + ch * 4);
            }
            cpa_commit();
        }

        // ---- phase 1: full logits, inline exp; warp does 4 j rows ----
#pragma unroll
        for (int jj = 0; jj < 4; jj++) {
            const int jl = jq * 4 + jj;
            const int j = tt * TJ + jl;
            ulonglong2 kv[4];
#pragma unroll
            for (int u = 0; u < 4; u++)
                kv[u] = *(const ulonglong2*)&kn_s[buf][jl][4 * l + 128 * u];
            ull_t a2[4];
#pragma unroll
            for (int h = 0; h < 4; h++) a2[h] = 0ull;
#pragma unroll
            for (int h = 0; h < 4; h++)
#pragma unroll
                for (int u = 0; u < 4; u++) {
                    FMA2(a2[h], kv[u].x, qw[h][u].x);
                    FMA2(a2[h], kv[u].y, qw[h][u].y);
                }
            float v[4];
#pragma unroll
            for (int h = 0; h < 4; h++) {
                float lo, hi; UNPACK2(lo, hi, a2[h]); v[h] = lo + hi;
            }
#pragma unroll
            for (int h = 0; h < 2; h++) {
                float give = (l & 16) ? v[h] : v[h + 2];
                float keep = (l & 16) ? v[h + 2] : v[h];
                v[h] = keep + __shfl_xor_sync(0xffffffffu, give, 16);
            }
            {
                float give = (l & 8) ? v[0] : v[1];
                float keep = (l & 8) ? v[1] : v[0];
                v[0] = keep + __shfl_xor_sync(0xffffffffu, give, 8);
            }
            v[0] += __shfl_xor_sync(0xffffffffu, v[0], 4);
            v[0] += __shfl_xor_sync(0xffffffffu, v[0], 2);
            v[0] += __shfl_xor_sync(0xffffffffu, v[0], 1);
            if ((l & 7) == 0) {
                const int h = h0 + ((l >> 4) & 1) * 2 + ((l >> 3) & 1);
                float lg = (v[0] + pq_s[h][j]) * SCALING;
                float p = m8[h][j] ? __expf(lg) : 0.f;
                pq_s[h][j] = p;
                ull_t p2; PACK2(p2, p, p);
                pT2[jl][h] = p2;
            }
        }
        __syncthreads();   // p ready

        // ---- phase 3: s accumulation from same tile ----
        {
            const int h0p = g * 4;
#pragma unroll
            for (int jl = 0; jl < TJ; jl++) {
                ulonglong2 kv = *(const ulonglong2*)&kn_s[buf][jl][e0];
                ulonglong2 pa = *(const ulonglong2*)&pT2[jl][h0p];
                ulonglong2 pb = *(const ulonglong2*)&pT2[jl][h0p + 2];
                FMA2(accv[0][0], pa.x, kv.x); FMA2(accv[0][1], pa.x, kv.y);
                FMA2(accv[1][0], pa.y, kv.x); FMA2(accv[1][1], pa.y, kv.y);
                FMA2(accv[2][0], pb.x, kv.x); FMA2(accv[2][1], pb.x, kv.y);
                FMA2(accv[3][0], pb.y, kv.x); FMA2(accv[3][1], pb.y, kv.y);
            }
        }
        buf ^= 1;
    }

    // ---- normalization: warp w sums p over head w ----
    {
        float s = 0.f;
#pragma unroll
        for (int c = 0; c < 4; c++) s += pq_s[w][l + 32 * c];
#pragma unroll
        for (int off = 16; off; off >>= 1)
            s += __shfl_xor_sync(0xffffffffu, s, off);
        if (l == 0) inv_s[w] = 1.f / s;
    }
    __syncthreads();

    // ---- write s (normalized) ----
    {
        const int h0p = g * 4;
#pragma unroll
        for (int hh = 0; hh < 4; hh++) {
            float inv = inv_s[h0p + hh];
            float4 o;
            UNPACK2(o.x, o.y, accv[hh][0]);
            UNPACK2(o.z, o.w, accv[hh][1]);
            o.x *= inv; o.y *= inv; o.z *= inv; o.w *= inv;
            *(float4*)&g_s[(((size_t)(n * 8 + h0p + hh) * 128 + i)) * 512 + e0] = o;
        }
    }
    // ---- write normalized aw ----
#pragma unroll
    for (int u = 0; u < 4; u++) {
        int c = t + 256 * u;
        int h = c >> 7, j = c & 127;
        g_aw[(((size_t)(n * 8 + h) * 128 + i)) * 128 + j] = pq_s[h][j] * inv_s[h];
    }
}

// ---------------- K4b: attn GEMM, K-split x2 (round-10 tile, grid 256) ------
// BM=128, BN=64, BK=32; grid (16 n, 8 h, 2 khalf); thread = 8 rows x 4 cols.
// khalf 0 -> k in [0,320) -> g_attnA;  khalf 1 -> k in [320,640) -> g_attnB.
__global__ __launch_bounds__(256) void k4b_attn(const float* __restrict__ Wknow) {
    __shared__ float As[2][32][128];
    __shared__ float Bs[2][32][64];
    const int n = blockIdx.x;
    const int h = blockIdx.y;
    const int kbase = blockIdx.z * 320;
    float* gout = blockIdx.z ? g_attnB : g_attnA;
    const int t = threadIdx.x;
    const int ty = t >> 4, tx = t & 15;
    const int rr = t >> 1;            // A row
    const int kq = (t & 1) * 16;      // A col chunk

    const size_t bhrow = ((size_t)(n * 8 + h)) * 128;

    float4 pa[4], pb[2];
    auto gload = [&](int k0) {
        const float* p = (k0 < 128)
            ? &g_aw[(bhrow + rr) * 128 + k0 + kq]
            : &g_s[(bhrow + rr) * 512 + (k0 - 128) + kq];
        pa[0] = *(const float4*)p;
        pa[1] = *(const float4*)(p + 4);
        pa[2] = *(const float4*)(p + 8);
        pa[3] = *(const float4*)(p + 12);
        if (k0 < 128) {
            const int kr = t >> 3, dq = (t & 7) * 8;
            const float* q = &g_v[(bhrow + (k0 + kr)) * 64 + dq];
            pb[0] = *(const float4*)q;
            pb[1] = *(const float4*)(q + 4);
        } else {
            const int d = t >> 2, eq = (t & 3) * 8;
            const float* q = Wknow + (size_t)(h * 64 + d) * 512 + (k0 - 128) + eq;
            pb[0] = *(const float4*)q;
            pb[1] = *(const float4*)(q + 4);
        }
    };
    auto sstore = [&](int k0, int bf) {
#pragma unroll
        for (int c = 0; c < 4; c++) {
            As[bf][kq + 4 * c + 0][rr] = pa[c].x;
            As[bf][kq + 4 * c + 1][rr] = pa[c].y;
            As[bf][kq + 4 * c + 2][rr] = pa[c].z;
            As[bf][kq + 4 * c + 3][rr] = pa[c].w;
        }
        if (k0 < 128) {
            const int kr = t >> 3, dq = (t & 7) * 8;
            *(float4*)&Bs[bf][kr][dq]     = pb[0];
            *(float4*)&Bs[bf][kr][dq + 4] = pb[1];
        } else {
            const int d = t >> 2, eq = (t & 3) * 8;
            Bs[bf][eq + 0][d] = pb[0].x; Bs[bf][eq + 1][d] = pb[0].y;
            Bs[bf][eq + 2][d] = pb[0].z; Bs[bf][eq + 3][d] = pb[0].w;
            Bs[bf][eq + 4][d] = pb[1].x; Bs[bf][eq + 5][d] = pb[1].y;
            Bs[bf][eq + 6][d] = pb[1].z; Bs[bf][eq + 7][d] = pb[1].w;
        }
    };

    ull_t acc2[8][2];
#pragma unroll
    for (int a = 0; a < 8; a++) { acc2[a][0] = 0ull; acc2[a][1] = 0ull; }

    gload(kbase); sstore(kbase, 0); __syncthreads();
    int buf = 0;
#pragma unroll 1
    for (int k0 = kbase; k0 < kbase + 320; k0 += 32) {
        if (k0 < kbase + 288) gload(k0 + 32);
#pragma unroll
        for (int kk = 0; kk < 32; kk++) {
            float a[8];
            *(float4*)(a)     = *(float4*)&As[buf][kk][ty * 8];
            *(float4*)(a + 4) = *(float4*)&As[buf][kk][ty * 8 + 4];
            ulonglong2 b2 = *(ulonglong2*)&Bs[buf][kk][tx * 4];
#pragma unroll
            for (int p = 0; p < 8; p++) {
                ull_t ap; PACK2(ap, a[p], a[p]);
                FMA2(acc2[p][0], ap, b2.x);
                FMA2(acc2[p][1], ap, b2.y);
            }
        }
        if (k0 < kbase + 288) sstore(k0 + 32, buf ^ 1);
        __syncthreads();
        buf ^= 1;
    }
#pragma unroll
    for (int ry = 0; ry < 8; ry++) {
        const int i = ty * 8 + ry;
        float4 o;
        UNPACK2(o.x, o.y, acc2[ry][0]);
        UNPACK2(o.z, o.w, acc2[ry][1]);
        float* dst = gout + ((size_t)i * 16 + n) * 512 + h * 64 + tx * 4;
        *(float4*)dst = o;
    }
}

// ---------------- K5: gating  out = g*r + (1-g)*(attnA+attnB) ---------------
__global__ __launch_bounds__(128) void k5_gate(const float* __restrict__ Wbeta,
                                               float* __restrict__ out) {
    const int m = blockIdx.x;
    const int t = threadIdx.x;
    const int w = t >> 5, l = t & 31;
    __shared__ float red[4];
    __shared__ float a_s[512];

    const float* aA = g_attnA + (size_t)m * 512;
    const float* aB = g_attnB + (size_t)m * 512;
    const float* r = g_r + (size_t)m * 512;

    float z = 0.f;
#pragma unroll
    for (int c = 0; c < 4; c++) {
        int e = t + 128 * c;
        float av = aA[e] + aB[e];
        a_s[e] = av;
        float rv = r[e];
        z += Wbeta[e] * av + Wbeta[512 + e] * rv + Wbeta[1024 + e] * (av - rv);
    }
#pragma unroll
    for (int off = 16; off; off >>= 1)
        z += __shfl_xor_sync(0xffffffffu, z, off);
    if (l == 0) red[w] = z;
    __syncthreads();
    float zt = red[0] + red[1] + red[2] + red[3];
    float g = 1.f / (1.f + __expf(-zt));

#pragma unroll
    for (int c = 0; c < 4; c++) {
        int e = t + 128 * c;
        out[(size_t)m * 512 + e] = g * r[e] + (1.f - g) * a_s[e];
    }
}

// ---------------- launch -----------------------------------------------------
extern "C" void kernel_launch(void* const* d_in, const int* in_sizes, int n_in,
                              void* d_out, int out_size) {
    const float* x     = (const float*)d_in[0];
    const float* know  = (const float*)d_in[1];
    const int*   mask  = (const int*)d_in[2];
    const float* Wq    = (const float*)d_in[3];
    const float* Wk    = (const float*)d_in[4];
    const float* Wv    = (const float*)d_in[5];
    const float* Wknow = (const float*)d_in[6];
    const float* Wskip = (const float*)d_in[7];
    const float* Wbeta = (const float*)d_in[8];
    float* out = (float*)d_out;

    k1_proj<<<dim3(16, 16), 256>>>(x, Wq, Wk, Wv, Wskip);
    k23<<<640, 256>>>(Wknow);
    k34_onepass<<<2048, 256>>>(know, mask);
    k4b_attn<<<dim3(16, 8, 2), 256>>>(Wknow);
    k5_gate<<<2048, 128>>>(Wbeta, out);
}

// round 16
// speedup vs baseline: 1.1940x; 1.0215x over previous
#include <cuda_runtime.h>
#include <cstdint>

#define SLEN 128
#define BSZ  16
#define EMB  512
#define NHEAD 8
#define HDIM 64
#define BH   (BSZ*NHEAD)   // 128
#define NEG_INF (-1e9f)
#define SCALING 0.125f     // 1/sqrt(64)

// ---- f32x2 packed math (Blackwell) ----
#define FMA2(d, a, b) asm("fma.rn.f32x2 %0, %1, %2, %0;" : "+l"(d) : "l"(a), "l"(b))
#define PACK2(u, lo, hi) asm("mov.b64 %0, {%1, %2};" : "=l"(u) : "f"(lo), "f"(hi))
#define UNPACK2(lo, hi, u) asm("mov.b64 {%0, %1}, %2;" : "=f"(lo), "=f"(hi) : "l"(u))

typedef unsigned long long ull_t;

__device__ __forceinline__ void cpa16(uint32_t saddr, const void* gaddr) {
    asm volatile("cp.async.ca.shared.global [%0], [%1], 16;" :: "r"(saddr), "l"(gaddr));
}
__device__ __forceinline__ void cpa_commit() {
    asm volatile("cp.async.commit_group;");
}
__device__ __forceinline__ void cpa_wait_all() {
    asm volatile("cp.async.wait_group 0;");
}

// ---------------- scratch (device globals; no runtime alloc) ----------------
__device__ float g_q[BH*SLEN*HDIM];        // [b][i][d]
__device__ float g_k[BH*SLEN*HDIM];        // [b][j][d]
__device__ float g_v[BH*SLEN*HDIM];        // [b][j][d]
__device__ float g_r[SLEN*BSZ*EMB];        // [m][e]
__device__ float g_qW[BH*SLEN*EMB];        // [b][i][e]
__device__ float g_aw[BH*SLEN*SLEN];       // [b][i][j]  (qk base, then normalized aw)
__device__ float g_s[BH*SLEN*EMB];         // [b][i][e]
__device__ float g_attn[SLEN*BSZ*EMB];     // [m][e]

// ---------------- K1: fused projections  C = X(2048x512) @ W^T --------------
// round-9 structure with BK 16->32: same traffic, half the barriers (32 vs 64).
__global__ __launch_bounds__(256) void k1_proj(const float* __restrict__ x,
                                               const float* __restrict__ Wq,
                                               const float* __restrict__ Wk,
                                               const float* __restrict__ Wv,
                                               const float* __restrict__ Wskip) {
    __shared__ float As[32][128];
    __shared__ float Bs[32][128];
    const int m0 = blockIdx.y * 128;
    const int c0 = blockIdx.x * 128;
    const int sel = c0 >> 9;
    const float* W = (sel == 0) ? Wq : (sel == 1) ? Wk : (sel == 2) ? Wv : Wskip;
    const int e0 = c0 & 511;

    const int t  = threadIdx.x;
    const int ty = t >> 4, tx = t & 15;
    const int lr = t >> 1;
    const int lc = (t & 1) * 16;

    ull_t acc2[8][4];
#pragma unroll
    for (int a = 0; a < 8; a++)
#pragma unroll
        for (int b = 0; b < 4; b++) acc2[a][b] = 0ull;

    for (int k0 = 0; k0 < 512; k0 += 32) {
        const float* xr = x + (size_t)(m0 + lr) * 512 + k0 + lc;
        const float* wr = W + (size_t)(e0 + lr) * 512 + k0 + lc;
#pragma unroll
        for (int c = 0; c < 4; c++) {
            float4 a4 = *(const float4*)(xr + 4 * c);
            As[lc + 4 * c + 0][lr] = a4.x; As[lc + 4 * c + 1][lr] = a4.y;
            As[lc + 4 * c + 2][lr] = a4.z; As[lc + 4 * c + 3][lr] = a4.w;
            float4 b4 = *(const float4*)(wr + 4 * c);
            Bs[lc + 4 * c + 0][lr] = b4.x; Bs[lc + 4 * c + 1][lr] = b4.y;
            Bs[lc + 4 * c + 2][lr] = b4.z; Bs[lc + 4 * c + 3][lr] = b4.w;
        }
        __syncthreads();
#pragma unroll
        for (int kk = 0; kk < 32; kk++) {
            float a[8];
            *(float4*)(a)     = *(float4*)&As[kk][ty * 8];
            *(float4*)(a + 4) = *(float4*)&As[kk][ty * 8 + 4];
            ulonglong2 bA = *(ulonglong2*)&Bs[kk][tx * 8];
            ulonglong2 bB = *(ulonglong2*)&Bs[kk][tx * 8 + 4];
#pragma unroll
            for (int p = 0; p < 8; p++) {
                ull_t ap; PACK2(ap, a[p], a[p]);
                FMA2(acc2[p][0], ap, bA.x);
                FMA2(acc2[p][1], ap, bA.y);
                FMA2(acc2[p][2], ap, bB.x);
                FMA2(acc2[p][3], ap, bB.y);
            }
        }
        __syncthreads();
    }

    const int ecol = e0 + tx * 8;
    const int h = ecol >> 6;
    const int d0 = ecol & 63;
#pragma unroll
    for (int ry = 0; ry < 8; ry++) {
        const int m = m0 + ty * 8 + ry;
        const int i = m >> 4, n = m & 15;
        float o[8];
#pragma unroll
        for (int q = 0; q < 4; q++) UNPACK2(o[2*q], o[2*q+1], acc2[ry][q]);
        if (sel == 3) {
            float* dst = g_r + (size_t)m * 512 + ecol;
            *(float4*)dst       = *(float4*)&o[0];
            *(float4*)(dst + 4) = *(float4*)&o[4];
        } else {
            float* base = (sel == 0) ? g_q : (sel == 1) ? g_k : g_v;
            float* dst = base + ((size_t)(n * 8 + h) * 128 + i) * 64 + d0;
            *(float4*)dst       = *(float4*)&o[0];
            *(float4*)(dst + 4) = *(float4*)&o[4];
        }
    }
}

// ---------------- K23: merged qW GEMM (blocks 0..511) + q.k base (512..639) -
__global__ __launch_bounds__(256) void k23(const float* __restrict__ Wknow) {
    __shared__ float sm[8192];   // 32 KB, unioned
    const int t = threadIdx.x;
    const int bx = blockIdx.x;

    if (bx < 512) {
        float (*As)[128] = (float(*)[128])sm;
        float (*Bs)[128] = (float(*)[128])(sm + 16 * 128);
        const int h = bx >> 6;
        const int sub = bx & 63;
        const int m0 = (sub & 15) * 128;
        const int e0t = (sub >> 4) * 128;

        const int ty = t >> 4, tx = t & 15;
        const int lr = t >> 1;
        const int lc = (t & 1) * 8;
        const int dr = t >> 4;
        const int ec = (t & 15) * 8;

        ull_t acc2[8][4];
#pragma unroll
        for (int a = 0; a < 8; a++)
#pragma unroll
            for (int b = 0; b < 4; b++) acc2[a][b] = 0ull;

        for (int k0 = 0; k0 < 64; k0 += 16) {
            {
                const int m = m0 + lr;
                const int n = m >> 7, i = m & 127;
                const float* ar = &g_q[((size_t)(n * 8 + h) * 128 + i) * 64 + k0 + lc];
                float4 a0 = *(const float4*)ar;
                float4 a1 = *(const float4*)(ar + 4);
                As[lc + 0][lr] = a0.x; As[lc + 1][lr] = a0.y;
                As[lc + 2][lr] = a0.z; As[lc + 3][lr] = a0.w;
                As[lc + 4][lr] = a1.x; As[lc + 5][lr] = a1.y;
                As[lc + 6][lr] = a1.z; As[lc + 7][lr] = a1.w;
            }
            {
                const float* br = Wknow + (size_t)(h * 64 + k0 + dr) * 512 + e0t + ec;
                float4 b0 = *(const float4*)br;
                float4 b1 = *(const float4*)(br + 4);
                *(float4*)&Bs[dr][ec]     = b0;
                *(float4*)&Bs[dr][ec + 4] = b1;
            }
            __syncthreads();
#pragma unroll
            for (int kk = 0; kk < 16; kk++) {
                float a[8];
                *(float4*)(a)     = *(float4*)&As[kk][ty * 8];
                *(float4*)(a + 4) = *(float4*)&As[kk][ty * 8 + 4];
                ulonglong2 bA = *(ulonglong2*)&Bs[kk][tx * 8];
                ulonglong2 bB = *(ulonglong2*)&Bs[kk][tx * 8 + 4];
#pragma unroll
                for (int p = 0; p < 8; p++) {
                    ull_t ap; PACK2(ap, a[p], a[p]);
                    FMA2(acc2[p][0], ap, bA.x);
                    FMA2(acc2[p][1], ap, bA.y);
                    FMA2(acc2[p][2], ap, bB.x);
                    FMA2(acc2[p][3], ap, bB.y);
                }
            }
            __syncthreads();
        }
#pragma unroll
        for (int ry = 0; ry < 8; ry++) {
            const int m = m0 + ty * 8 + ry;
            const int n = m >> 7, i = m & 127;
            float o[8];
#pragma unroll
            for (int q = 0; q < 4; q++) UNPACK2(o[2*q], o[2*q+1], acc2[ry][q]);
            float* dst = &g_qW[((size_t)(n * 8 + h) * 128 + i) * 512 + e0t + tx * 8];
            *(float4*)dst       = *(float4*)&o[0];
            *(float4*)(dst + 4) = *(float4*)&o[4];
        }
    } else {
        float (*qT)[128] = (float(*)[128])sm;
        float (*kT)[128] = (float(*)[128])(sm + 32 * 128);
        const int b = bx - 512;
        const int ty = t >> 4, tx = t & 15;

        float acc[8][8];
#pragma unroll
        for (int p = 0; p < 8; p++)
#pragma unroll
            for (int q = 0; q < 8; q++) acc[p][q] = 0.f;

        for (int d0 = 0; d0 < 64; d0 += 32) {
#pragma unroll
            for (int u = 0; u < 4; u++) {
                int ii = (t >> 3) + 32 * u;
                int d4 = (t & 7) * 4;
                float4 a = *(const float4*)&g_q[((size_t)b * 128 + ii) * 64 + d0 + d4];
                qT[d4 + 0][ii] = a.x; qT[d4 + 1][ii] = a.y;
                qT[d4 + 2][ii] = a.z; qT[d4 + 3][ii] = a.w;
                float4 bb = *(const float4*)&g_k[((size_t)b * 128 + ii) * 64 + d0 + d4];
                kT[d4 + 0][ii] = bb.x; kT[d4 + 1][ii] = bb.y;
                kT[d4 + 2][ii] = bb.z; kT[d4 + 3][ii] = bb.w;
            }
            __syncthreads();
#pragma unroll
            for (int d = 0; d < 32; d++) {
                float a[8], bl[8];
                *(float4*)(a)      = *(float4*)&qT[d][ty * 8];
                *(float4*)(a + 4)  = *(float4*)&qT[d][ty * 8 + 4];
                *(float4*)(bl)     = *(float4*)&kT[d][tx * 8];
                *(float4*)(bl + 4) = *(float4*)&kT[d][tx * 8 + 4];
#pragma unroll
                for (int p = 0; p < 8; p++)
#pragma unroll
                    for (int q = 0; q < 8; q++) acc[p][q] += a[p] * bl[q];
            }
            __syncthreads();
        }
#pragma unroll
        for (int p = 0; p < 8; p++) {
            float* dst = &g_aw[((size_t)b * 128 + ty * 8 + p) * 128 + tx * 8];
            *(float4*)dst       = *(float4*)&acc[p][0];
            *(float4*)(dst + 4) = *(float4*)&acc[p][4];
        }
    }
}

// ---------------- K34: ONE-PASS logits + exp + s-accum over know ------------
// (round-7/11 version: best measured, FROZEN)
#define TJ 16
__global__ __launch_bounds__(256, 2) void k34_onepass(const float* __restrict__ know,
                                                      const int* __restrict__ mask) {
    __shared__ float kn_s[2][TJ][512];   // 64 KB (double buffer)
    __shared__ ull_t pT2[TJ][8];         // 1 KB  (packed (p,p))
    __shared__ float pq_s[8][128];       // 4 KB  (qk base -> unnormalized p)
    __shared__ unsigned char m8[8][128]; // 1 KB
    __shared__ float inv_s[8];

    const int n = blockIdx.x >> 7;
    const int i = blockIdx.x & 127;
    const int t = threadIdx.x, w = t >> 5, l = t & 31;
    const int hg = w & 1, jq = w >> 1;           // phase-1 warp role
    const int h0 = hg * 4;
    const int g = t >> 7;                        // phase-3 h-group (0/1)
    const int e0 = (t & 127) << 2;               // phase-3 e-chunk

    // ---- preload q.k base (into pq_s) + mask ----
    {
        int h = t >> 5, j0 = (t & 31) << 2;
        *(float4*)&pq_s[h][j0] =
            *(const float4*)&g_aw[(((size_t)(n * 8 + h) * 128 + i)) * 128 + j0];
        int4 mm = *(const int4*)&mask[(((size_t)(n * 8 + h) * 128 + i)) * 128 + j0];
        uchar4 mb;
        mb.x = (unsigned char)(mm.x != 0); mb.y = (unsigned char)(mm.y != 0);
        mb.z = (unsigned char)(mm.z != 0); mb.w = (unsigned char)(mm.w != 0);
        *(uchar4*)&m8[h][j0] = mb;
    }

    // ---- qW slices into registers: 4 heads x full 512e, e = 4l + 128u ----
    ulonglong2 qw[4][4];
#pragma unroll
    for (int h = 0; h < 4; h++) {
        const float* qb = &g_qW[(((size_t)(n * 8 + h0 + h) * 128 + i)) * 512 + 4 * l];
#pragma unroll
        for (int u = 0; u < 4; u++)
            qw[h][u] = *(const ulonglong2*)(qb + 128 * u);
    }

    const float* knbase = know + ((size_t)n * 16384 + (size_t)i * 128) * 512;
    const uint32_t kn_sa = (uint32_t)__cvta_generic_to_shared(&kn_s[0][0][0]);

    ull_t accv[4][2];
#pragma unroll
    for (int hh = 0; hh < 4; hh++) { accv[hh][0] = 0ull; accv[hh][1] = 0ull; }

    // ---- prologue: stage tile 0 into buf 0 via cp.async ----
#pragma unroll
    for (int u = 0; u < 8; u++) {
        int c = t + 256 * u;
        int r = c >> 7, ch = c & 127;
        cpa16(kn_sa + (uint32_t)(r * 2048 + ch * 16),
              knbase + (size_t)r * 512 + ch * 4);
    }
    cpa_commit();

    int buf = 0;
#pragma unroll 1
    for (int tt = 0; tt < 8; tt++) {
        cpa_wait_all();
        __syncthreads();   // tile[buf] visible; prev phase3 done with pT2

        if (tt < 7) {
            const float* nb = knbase + (size_t)(tt + 1) * TJ * 512;
            const uint32_t sb = kn_sa + (uint32_t)((buf ^ 1) * TJ * 2048);
#pragma unroll
            for (int u = 0; u < 8; u++) {
                int c = t + 256 * u;
                int r = c >> 7, ch = c & 127;
                cpa16(sb + (uint32_t)(r * 2048 + ch * 16),
                      nb + (size_t)r * 512 + ch * 4);
            }
            cpa_commit();
        }

        // ---- phase 1: full logits, inline exp; warp does 4 j rows ----
#pragma unroll
        for (int jj = 0; jj < 4; jj++) {
            const int jl = jq * 4 + jj;
            const int j = tt * TJ + jl;
            ulonglong2 kv[4];
#pragma unroll
            for (int u = 0; u < 4; u++)
                kv[u] = *(const ulonglong2*)&kn_s[buf][jl][4 * l + 128 * u];
            ull_t a2[4];
#pragma unroll
            for (int h = 0; h < 4; h++) a2[h] = 0ull;
#pragma unroll
            for (int h = 0; h < 4; h++)
#pragma unroll
                for (int u = 0; u < 4; u++) {
                    FMA2(a2[h], kv[u].x, qw[h][u].x);
                    FMA2(a2[h], kv[u].y, qw[h][u].y);
                }
            float v[4];
#pragma unroll
            for (int h = 0; h < 4; h++) {
                float lo, hi; UNPACK2(lo, hi, a2[h]); v[h] = lo + hi;
            }
#pragma unroll
            for (int h = 0; h < 2; h++) {
                float give = (l & 16) ? v[h] : v[h + 2];
                float keep = (l & 16) ? v[h + 2] : v[h];
                v[h] = keep + __shfl_xor_sync(0xffffffffu, give, 16);
            }
            {
                float give = (l & 8) ? v[0] : v[1];
                float keep = (l & 8) ? v[1] : v[0];
                v[0] = keep + __shfl_xor_sync(0xffffffffu, give, 8);
            }
            v[0] += __shfl_xor_sync(0xffffffffu, v[0], 4);
            v[0] += __shfl_xor_sync(0xffffffffu, v[0], 2);
            v[0] += __shfl_xor_sync(0xffffffffu, v[0], 1);
            if ((l & 7) == 0) {
                const int h = h0 + ((l >> 4) & 1) * 2 + ((l >> 3) & 1);
                float lg = (v[0] + pq_s[h][j]) * SCALING;
                float p = m8[h][j] ? __expf(lg) : 0.f;
                pq_s[h][j] = p;
                ull_t p2; PACK2(p2, p, p);
                pT2[jl][h] = p2;
            }
        }
        __syncthreads();   // p ready

        // ---- phase 3: s accumulation from same tile ----
        {
            const int h0p = g * 4;
#pragma unroll
            for (int jl = 0; jl < TJ; jl++) {
                ulonglong2 kv = *(const ulonglong2*)&kn_s[buf][jl][e0];
                ulonglong2 pa = *(const ulonglong2*)&pT2[jl][h0p];
                ulonglong2 pb = *(const ulonglong2*)&pT2[jl][h0p + 2];
                FMA2(accv[0][0], pa.x, kv.x); FMA2(accv[0][1], pa.x, kv.y);
                FMA2(accv[1][0], pa.y, kv.x); FMA2(accv[1][1], pa.y, kv.y);
                FMA2(accv[2][0], pb.x, kv.x); FMA2(accv[2][1], pb.x, kv.y);
                FMA2(accv[3][0], pb.y, kv.x); FMA2(accv[3][1], pb.y, kv.y);
            }
        }
        buf ^= 1;
    }

    // ---- normalization: warp w sums p over head w ----
    {
        float s = 0.f;
#pragma unroll
        for (int c = 0; c < 4; c++) s += pq_s[w][l + 32 * c];
#pragma unroll
        for (int off = 16; off; off >>= 1)
            s += __shfl_xor_sync(0xffffffffu, s, off);
        if (l == 0) inv_s[w] = 1.f / s;
    }
    __syncthreads();

    // ---- write s (normalized) ----
    {
        const int h0p = g * 4;
#pragma unroll
        for (int hh = 0; hh < 4; hh++) {
            float inv = inv_s[h0p + hh];
            float4 o;
            UNPACK2(o.x, o.y, accv[hh][0]);
            UNPACK2(o.z, o.w, accv[hh][1]);
            o.x *= inv; o.y *= inv; o.z *= inv; o.w *= inv;
            *(float4*)&g_s[(((size_t)(n * 8 + h0p + hh) * 128 + i)) * 512 + e0] = o;
        }
    }
    // ---- write normalized aw ----
#pragma unroll
    for (int u = 0; u < 4; u++) {
        int c = t + 256 * u;
        int h = c >> 7, j = c & 127;
        g_aw[(((size_t)(n * 8 + h) * 128 + i)) * 128 + j] = pq_s[h][j] * inv_s[h];
    }
}

// ---------------- K4b: attn GEMM, reg-double-buffered (1 bar/step) ----------
// (round-10 measured version: 43.1us, FROZEN)
__global__ __launch_bounds__(256) void k4b_attn(const float* __restrict__ Wknow) {
    __shared__ float As[2][32][128];
    __shared__ float Bs[2][32][64];
    const int n = blockIdx.x;
    const int h = blockIdx.y;
    const int t = threadIdx.x;
    const int ty = t >> 4, tx = t & 15;
    const int rr = t >> 1;            // A row
    const int kq = (t & 1) * 16;      // A col chunk

    const size_t bhrow = ((size_t)(n * 8 + h)) * 128;

    float4 pa[4], pb[2];
    auto gload = [&](int k0) {
        const float* p = (k0 < 128)
            ? &g_aw[(bhrow + rr) * 128 + k0 + kq]
            : &g_s[(bhrow + rr) * 512 + (k0 - 128) + kq];
        pa[0] = *(const float4*)p;
        pa[1] = *(const float4*)(p + 4);
        pa[2] = *(const float4*)(p + 8);
        pa[3] = *(const float4*)(p + 12);
        if (k0 < 128) {
            const int kr = t >> 3, dq = (t & 7) * 8;
            const float* q = &g_v[(bhrow + (k0 + kr)) * 64 + dq];
            pb[0] = *(const float4*)q;
            pb[1] = *(const float4*)(q + 4);
        } else {
            const int d = t >> 2, eq = (t & 3) * 8;
            const float* q = Wknow + (size_t)(h * 64 + d) * 512 + (k0 - 128) + eq;
            pb[0] = *(const float4*)q;
            pb[1] = *(const float4*)(q + 4);
        }
    };
    auto sstore = [&](int k0, int bf) {
#pragma unroll
        for (int c = 0; c < 4; c++) {
            As[bf][kq + 4 * c + 0][rr] = pa[c].x;
            As[bf][kq + 4 * c + 1][rr] = pa[c].y;
            As[bf][kq + 4 * c + 2][rr] = pa[c].z;
            As[bf][kq + 4 * c + 3][rr] = pa[c].w;
        }
        if (k0 < 128) {
            const int kr = t >> 3, dq = (t & 7) * 8;
            *(float4*)&Bs[bf][kr][dq]     = pb[0];
            *(float4*)&Bs[bf][kr][dq + 4] = pb[1];
        } else {
            const int d = t >> 2, eq = (t & 3) * 8;
            Bs[bf][eq + 0][d] = pb[0].x; Bs[bf][eq + 1][d] = pb[0].y;
            Bs[bf][eq + 2][d] = pb[0].z; Bs[bf][eq + 3][d] = pb[0].w;
            Bs[bf][eq + 4][d] = pb[1].x; Bs[bf][eq + 5][d] = pb[1].y;
            Bs[bf][eq + 6][d] = pb[1].z; Bs[bf][eq + 7][d] = pb[1].w;
        }
    };

    ull_t acc2[8][2];
#pragma unroll
    for (int a = 0; a < 8; a++) { acc2[a][0] = 0ull; acc2[a][1] = 0ull; }

    gload(0); sstore(0, 0); __syncthreads();
    int buf = 0;
#pragma unroll 1
    for (int k0 = 0; k0 < 640; k0 += 32) {
        if (k0 < 608) gload(k0 + 32);
#pragma unroll
        for (int kk = 0; kk < 32; kk++) {
            float a[8];
            *(float4*)(a)     = *(float4*)&As[buf][kk][ty * 8];
            *(float4*)(a + 4) = *(float4*)&As[buf][kk][ty * 8 + 4];
            ulonglong2 b2 = *(ulonglong2*)&Bs[buf][kk][tx * 4];
#pragma unroll
            for (int p = 0; p < 8; p++) {
                ull_t ap; PACK2(ap, a[p], a[p]);
                FMA2(acc2[p][0], ap, b2.x);
                FMA2(acc2[p][1], ap, b2.y);
            }
        }
        if (k0 < 608) sstore(k0 + 32, buf ^ 1);
        __syncthreads();
        buf ^= 1;
    }
#pragma unroll
    for (int ry = 0; ry < 8; ry++) {
        const int i = ty * 8 + ry;
        float4 o;
        UNPACK2(o.x, o.y, acc2[ry][0]);
        UNPACK2(o.z, o.w, acc2[ry][1]);
        float* dst = g_attn + ((size_t)i * 16 + n) * 512 + h * 64 + tx * 4;
        *(float4*)dst = o;
    }
}

// ---------------- K5: gating  out = g*r + (1-g)*attn ------------------------
__global__ __launch_bounds__(128) void k5_gate(const float* __restrict__ Wbeta,
                                               float* __restrict__ out) {
    const int m = blockIdx.x;
    const int t = threadIdx.x;
    const int w = t >> 5, l = t & 31;
    __shared__ float red[4];

    const float* a = g_attn + (size_t)m * 512;
    const float* r = g_r + (size_t)m * 512;

    float z = 0.f;
#pragma unroll
    for (int c = 0; c < 4; c++) {
        int e = t + 128 * c;
        float av = a[e], rv = r[e];
        z += Wbeta[e] * av + Wbeta[512 + e] * rv + Wbeta[1024 + e] * (av - rv);
    }
#pragma unroll
    for (int off = 16; off; off >>= 1)
        z += __shfl_xor_sync(0xffffffffu, z, off);
    if (l == 0) red[w] = z;
    __syncthreads();
    float zt = red[0] + red[1] + red[2] + red[3];
    float g = 1.f / (1.f + __expf(-zt));

#pragma unroll
    for (int c = 0; c < 4; c++) {
        int e = t + 128 * c;
        out[(size_t)m * 512 + e] = g * r[e] + (1.f - g) * a[e];
    }
}

// ---------------- launch -----------------------------------------------------
extern "C" void kernel_launch(void* const* d_in, const int* in_sizes, int n_in,
                              void* d_out, int out_size) {
    const float* x     = (const float*)d_in[0];
    const float* know  = (const float*)d_in[1];
    const int*   mask  = (const int*)d_in[2];
    const float* Wq    = (const float*)d_in[3];
    const float* Wk    = (const float*)d_in[4];
    const float* Wv    = (const float*)d_in[5];
    const float* Wknow = (const float*)d_in[6];
    const float* Wskip = (const float*)d_in[7];
    const float* Wbeta = (const float*)d_in[8];
    float* out = (float*)d_out;

    k1_proj<<<dim3(16, 16), 256>>>(x, Wq, Wk, Wv, Wskip);
    k23<<<640, 256>>>(Wknow);
    k34_onepass<<<2048, 256>>>(know, mask);
    k4b_attn<<<dim3(16, 8), 256>>>(Wknow);
    k5_gate<<<2048, 128>>>(Wbeta, out);
}